// round 1
// baseline (speedup 1.0000x reference)
#include <cuda_runtime.h>
#include <cuda_bf16.h>

#define T_  4096
#define B_  4
#define D_  1024
#define H_  8
#define HD_ 128
#define R_  (T_*B_)   // 16384 rows

// ---------------- scratch (static device arrays; no runtime allocation) ----
__device__ __align__(16) float g_xn [(size_t)R_*D_];
__device__ __align__(16) float g_xtn[(size_t)R_*D_];
__device__ __align__(16) float g_q  [(size_t)R_*D_];
__device__ __align__(16) float g_k  [(size_t)R_*D_];
__device__ __align__(16) float g_v  [(size_t)R_*D_];
__device__ __align__(16) float g_pmax[8*B_*D_];
__device__ __align__(16) float g_psum[8*B_*D_];
__device__ __align__(16) float g_cmax[B_*D_];
__device__ __align__(16) float g_csum[B_*D_];
__device__ __align__(16) float g_attp[32ull*B_*H_*HD_*HD_];  // [split][bh][d][l]
__device__ __align__(16) float g_att [(size_t)B_*H_*HD_*HD_]; // [bh][d][l]

// ---------------- LayerNorm (both branches, shared mean/var) ---------------
__global__ void ln_kernel(const float* __restrict__ x,
                          const float* __restrict__ nw, const float* __restrict__ nb,
                          const float* __restrict__ tw, const float* __restrict__ tb) {
    int rin = blockIdx.x;            // t*B + b (input layout (T,B,D))
    int t = rin / B_, b = rin % B_;
    const float* xr = x + (size_t)rin * D_;
    int tid = threadIdx.x;

    float v[4];
    float s = 0.f, s2 = 0.f;
#pragma unroll
    for (int j = 0; j < 4; j++) {
        v[j] = xr[tid + j*256];
        s  += v[j];
        s2 += v[j]*v[j];
    }
    __shared__ float red[40];
#pragma unroll
    for (int o = 16; o; o >>= 1) {
        s  += __shfl_xor_sync(0xffffffffu, s,  o);
        s2 += __shfl_xor_sync(0xffffffffu, s2, o);
    }
    if ((tid & 31) == 0) { red[tid>>5] = s; red[8 + (tid>>5)] = s2; }
    __syncthreads();
    if (tid < 32) {
        float a = (tid < 8) ? red[tid]     : 0.f;
        float c = (tid < 8) ? red[8 + tid] : 0.f;
#pragma unroll
        for (int o = 4; o; o >>= 1) {
            a += __shfl_xor_sync(0xffffffffu, a, o);
            c += __shfl_xor_sync(0xffffffffu, c, o);
        }
        if (tid == 0) { red[32] = a; red[33] = c; }
    }
    __syncthreads();
    float mean = red[32] * (1.f / D_);
    float var  = red[33] * (1.f / D_) - mean*mean;
    float rstd = rsqrtf(var + 1e-5f);

    size_t ro = ((size_t)b*T_ + t) * D_;   // b-major row order downstream
#pragma unroll
    for (int j = 0; j < 4; j++) {
        int d = tid + j*256;
        float z = (v[j] - mean) * rstd;
        g_xn [ro + d] = z * nw[d] + nb[d];
        g_xtn[ro + d] = z * tw[d] + tb[d];
    }
}

// ---------------- tf32 tensor-core GEMM:  C = A @ W^T + bias ---------------
__device__ __forceinline__ unsigned f2t(float f) {
    unsigned u; asm("cvt.rna.tf32.f32 %0, %1;" : "=r"(u) : "f"(f)); return u;
}

__global__ void __launch_bounds__(256)
gemm_tf32(int mode, const float* __restrict__ W, const float* __restrict__ bias) {
    const float* A = (mode == 0) ? g_xn : g_xtn;
    float*       C = (mode == 0) ? g_q : (mode == 1 ? g_k : g_v);
    const int K = D_, N = D_;

    __shared__ __align__(16) unsigned As[128][36];
    __shared__ __align__(16) unsigned Bs[128][36];

    int tid  = threadIdx.x;
    int lane = tid & 31, wid = tid >> 5;
    int wm = wid >> 2, wn = wid & 3;          // 2 x 4 warps -> warp tile 64x32
    int grp = lane >> 2, tg = lane & 3;
    int bm = blockIdx.y * 128, bn = blockIdx.x * 128;

    float acc[4][4][4];
#pragma unroll
    for (int i = 0; i < 4; i++)
#pragma unroll
        for (int j = 0; j < 4; j++)
#pragma unroll
            for (int q = 0; q < 4; q++) acc[i][j][q] = 0.f;

    for (int k0 = 0; k0 < K; k0 += 32) {
#pragma unroll
        for (int i = 0; i < 4; i++) {
            int idx = tid + i*256;
            int row = idx >> 3, seg = idx & 7;
            float4 va = *(const float4*)(A + (size_t)(bm + row)*K + k0 + seg*4);
            As[row][seg*4+0] = f2t(va.x); As[row][seg*4+1] = f2t(va.y);
            As[row][seg*4+2] = f2t(va.z); As[row][seg*4+3] = f2t(va.w);
            float4 vb = *(const float4*)(W + (size_t)(bn + row)*K + k0 + seg*4);
            Bs[row][seg*4+0] = f2t(vb.x); Bs[row][seg*4+1] = f2t(vb.y);
            Bs[row][seg*4+2] = f2t(vb.z); Bs[row][seg*4+3] = f2t(vb.w);
        }
        __syncthreads();
#pragma unroll
        for (int kk = 0; kk < 4; kk++) {
            unsigned a[4][4], bb[4][2];
#pragma unroll
            for (int mi = 0; mi < 4; mi++) {
                int r0 = wm*64 + mi*16 + grp;
                a[mi][0] = As[r0    ][kk*8 + tg    ];
                a[mi][1] = As[r0 + 8][kk*8 + tg    ];
                a[mi][2] = As[r0    ][kk*8 + tg + 4];
                a[mi][3] = As[r0 + 8][kk*8 + tg + 4];
            }
#pragma unroll
            for (int ni = 0; ni < 4; ni++) {
                int c0 = wn*32 + ni*8 + grp;
                bb[ni][0] = Bs[c0][kk*8 + tg    ];
                bb[ni][1] = Bs[c0][kk*8 + tg + 4];
            }
#pragma unroll
            for (int mi = 0; mi < 4; mi++)
#pragma unroll
                for (int ni = 0; ni < 4; ni++) {
                    asm volatile(
                        "mma.sync.aligned.m16n8k8.row.col.f32.tf32.tf32.f32 "
                        "{%0,%1,%2,%3}, {%4,%5,%6,%7}, {%8,%9}, {%0,%1,%2,%3};"
                        : "+f"(acc[mi][ni][0]), "+f"(acc[mi][ni][1]),
                          "+f"(acc[mi][ni][2]), "+f"(acc[mi][ni][3])
                        : "r"(a[mi][0]), "r"(a[mi][1]), "r"(a[mi][2]), "r"(a[mi][3]),
                          "r"(bb[ni][0]), "r"(bb[ni][1]));
                }
        }
        __syncthreads();
    }

#pragma unroll
    for (int mi = 0; mi < 4; mi++)
#pragma unroll
        for (int ni = 0; ni < 4; ni++) {
            int row = bm + wm*64 + mi*16 + grp;
            int col = bn + wn*32 + ni*8 + tg*2;
            float b0 = bias[col], b1 = bias[col + 1];
            C[(size_t)row*N + col    ] = acc[mi][ni][0] + b0;
            C[(size_t)row*N + col + 1] = acc[mi][ni][1] + b1;
            C[(size_t)(row+8)*N + col    ] = acc[mi][ni][2] + b0;
            C[(size_t)(row+8)*N + col + 1] = acc[mi][ni][3] + b1;
        }
}

// ---------------- k time-softmax stats (per (b, d) column over T) ----------
__global__ void kstats_part() {
    int cidx = blockIdx.x*256 + threadIdx.x;   // 0..B*D-1
    int sp = blockIdx.y;                        // 0..7
    int b = cidx / D_, d = cidx % D_;
    int t0 = sp * (T_/8);
    const float* base = g_k + ((size_t)b*T_ + t0)*D_ + d;
    float m = -1e30f, s = 0.f;
    for (int t = 0; t < T_/8; t++) {
        float val = base[(size_t)t * D_];
        float nm = fmaxf(m, val);
        s = s * __expf(m - nm) + __expf(val - nm);
        m = nm;
    }
    g_pmax[sp*(B_*D_) + cidx] = m;
    g_psum[sp*(B_*D_) + cidx] = s;
}

__global__ void kstats_combine() {
    int cidx = blockIdx.x*256 + threadIdx.x;
    float m = -1e30f;
#pragma unroll
    for (int sp = 0; sp < 8; sp++) m = fmaxf(m, g_pmax[sp*(B_*D_) + cidx]);
    float s = 0.f;
#pragma unroll
    for (int sp = 0; sp < 8; sp++)
        s += g_psum[sp*(B_*D_) + cidx] * __expf(g_pmax[sp*(B_*D_) + cidx] - m);
    g_cmax[cidx] = m;
    g_csum[cidx] = s;
}

// ---------------- state:  attp = sum_t exp(k - max) * v  (split over T) ----
__global__ void __launch_bounds__(256) stage5_partial() {
    int bh = blockIdx.x;               // 0..31
    int b = bh >> 3, h = bh & 7;
    int sp = blockIdx.y;               // 0..31, 128 t each

    __shared__ __align__(16) float ks[16][128];
    __shared__ __align__(16) float vs[16][128];

    int tid = threadIdx.x;
    int tx = tid & 15, ty = tid >> 4;  // 16x16 thread grid, 8x8 outputs each
    float acc[8][8];
#pragma unroll
    for (int i = 0; i < 8; i++)
#pragma unroll
        for (int j = 0; j < 8; j++) acc[i][j] = 0.f;

    for (int c = 0; c < 8; c++) {
        int t0 = sp*128 + c*16;
#pragma unroll
        for (int i = 0; i < 8; i++) {
            int idx = tid + i*256;
            int tt = idx >> 7, d = idx & 127;
            size_t off = ((size_t)(b*T_ + t0 + tt))*D_ + h*128 + d;
            ks[tt][d] = __expf(g_k[off] - g_cmax[b*D_ + h*128 + d]);
            vs[tt][d] = g_v[off];
        }
        __syncthreads();
#pragma unroll
        for (int tt = 0; tt < 16; tt++) {
            float kr[8], vr[8];
            *(float4*)&kr[0] = *(const float4*)&ks[tt][ty*8];
            *(float4*)&kr[4] = *(const float4*)&ks[tt][ty*8 + 4];
            *(float4*)&vr[0] = *(const float4*)&vs[tt][tx*8];
            *(float4*)&vr[4] = *(const float4*)&vs[tt][tx*8 + 4];
#pragma unroll
            for (int i = 0; i < 8; i++)
#pragma unroll
                for (int j = 0; j < 8; j++) acc[i][j] += kr[i]*vr[j];
        }
        __syncthreads();
    }

    float* outp = g_attp + ((size_t)sp*32 + bh)*16384;
#pragma unroll
    for (int i = 0; i < 8; i++) {
        float* orow = outp + (ty*8 + i)*128 + tx*8;
        *(float4*)&orow[0] = make_float4(acc[i][0], acc[i][1], acc[i][2], acc[i][3]);
        *(float4*)&orow[4] = make_float4(acc[i][4], acc[i][5], acc[i][6], acc[i][7]);
    }
}

// ---------------- reduce splits + apply time-softmax denominator ----------
__global__ void stage5_reduce() {
    int idx = blockIdx.x*256 + threadIdx.x;    // 0..B*H*128*128-1
    int bh = idx >> 14;
    int rem = idx & 16383;
    int d = rem >> 7;
    int b = bh >> 3, h = bh & 7;
    float s = 0.f;
#pragma unroll
    for (int sp = 0; sp < 32; sp++) s += g_attp[((size_t)sp*32 + bh)*16384 + rem];
    g_att[(size_t)bh*16384 + rem] = s / g_csum[b*D_ + h*128 + d];
}

// ---------------- apply:  y = softmax_hd(q) @ att  (fused) ----------------
__global__ void __launch_bounds__(256) stage6(float* __restrict__ out) {
    int rb = blockIdx.x;               // 128 row-blocks of 128
    int h  = blockIdx.y;               // head
    int r0 = rb * 128;
    int b  = r0 / T_;
    const float* attm = g_att + ((size_t)(b*H_ + h))*16384;

    __shared__ __align__(16) float qs[128][36];   // transposed: qs[d][rowlocal(<32)]

    int tid = threadIdx.x;
    int lane = tid & 31, wid = tid >> 5;
    int tx = tid & 31, ty = tid >> 5;  // output cols tx*4.., rows ty*4..

    for (int ch = 0; ch < 4; ch++) {
        int rbase = r0 + ch*32;
        // --- softmax over head-dim for 32 rows; store transposed ----------
#pragma unroll
        for (int rr = 0; rr < 4; rr++) {
            int rl = wid*4 + rr;
            const float* qrow = g_q + (size_t)(rbase + rl)*D_ + h*128;
            float e[4];
            float mx = -1e30f;
#pragma unroll
            for (int j = 0; j < 4; j++) { e[j] = qrow[lane + 32*j]; mx = fmaxf(mx, e[j]); }
#pragma unroll
            for (int o = 16; o; o >>= 1) mx = fmaxf(mx, __shfl_xor_sync(0xffffffffu, mx, o));
            float sm = 0.f;
#pragma unroll
            for (int j = 0; j < 4; j++) { e[j] = __expf(e[j] - mx); sm += e[j]; }
#pragma unroll
            for (int o = 16; o; o >>= 1) sm += __shfl_xor_sync(0xffffffffu, sm, o);
            float inv = 1.f / sm;
#pragma unroll
            for (int j = 0; j < 4; j++) qs[lane + 32*j][rl] = e[j] * inv;
        }
        __syncthreads();

        // --- 32x128 GEMM against att (att rows hot in L1) ------------------
        float acc[4][4];
#pragma unroll
        for (int i = 0; i < 4; i++)
#pragma unroll
            for (int j = 0; j < 4; j++) acc[i][j] = 0.f;

#pragma unroll 4
        for (int d = 0; d < 128; d++) {
            float4 av = *(const float4*)(attm + d*128 + tx*4);
            float4 qv = *(const float4*)&qs[d][ty*4];
            acc[0][0] += qv.x*av.x; acc[0][1] += qv.x*av.y; acc[0][2] += qv.x*av.z; acc[0][3] += qv.x*av.w;
            acc[1][0] += qv.y*av.x; acc[1][1] += qv.y*av.y; acc[1][2] += qv.y*av.z; acc[1][3] += qv.y*av.w;
            acc[2][0] += qv.z*av.x; acc[2][1] += qv.z*av.y; acc[2][2] += qv.z*av.z; acc[2][3] += qv.z*av.w;
            acc[3][0] += qv.w*av.x; acc[3][1] += qv.w*av.y; acc[3][2] += qv.w*av.z; acc[3][3] += qv.w*av.w;
        }

#pragma unroll
        for (int i = 0; i < 4; i++) {
            float4 w = make_float4(acc[i][0], acc[i][1], acc[i][2], acc[i][3]);
            *(float4*)(out + (size_t)(rbase + ty*4 + i)*D_ + h*128 + tx*4) = w;
        }
        __syncthreads();
    }
}

// ---------------------------------------------------------------------------
extern "C" void kernel_launch(void* const* d_in, const int* in_sizes, int n_in,
                              void* d_out, int out_size) {
    const float* x  = (const float*)d_in[0];
    const float* nw = (const float*)d_in[1];
    const float* nb = (const float*)d_in[2];
    const float* tw = (const float*)d_in[3];
    const float* tb = (const float*)d_in[4];
    const float* Wq = (const float*)d_in[5];
    const float* bq = (const float*)d_in[6];
    const float* Wk = (const float*)d_in[7];
    const float* bk = (const float*)d_in[8];
    const float* Wv = (const float*)d_in[9];
    const float* bv = (const float*)d_in[10];
    float* out = (float*)d_out;

    ln_kernel<<<R_, 256>>>(x, nw, nb, tw, tb);

    dim3 gg(D_/128, R_/128);             // (8, 128)
    gemm_tf32<<<gg, 256>>>(0, Wq, bq);   // q  = xn  @ Wq^T + bq
    gemm_tf32<<<gg, 256>>>(1, Wk, bk);   // k  = xtn @ Wk^T + bk
    gemm_tf32<<<gg, 256>>>(2, Wv, bv);   // v  = xtn @ Wv^T + bv

    kstats_part<<<dim3((B_*D_)/256, 8), 256>>>();
    kstats_combine<<<(B_*D_)/256, 256>>>();

    stage5_partial<<<dim3(B_*H_, 32), 256>>>();
    stage5_reduce<<<(B_*H_*HD_*HD_)/256, 256>>>();   // 2048 blocks

    stage6<<<dim3(R_/128, H_), 256>>>(out);
}

// round 2
// speedup vs baseline: 1.3869x; 1.3869x over previous
#include <cuda_runtime.h>
#include <cuda_bf16.h>

#define T_  4096
#define B_  4
#define D_  1024
#define H_  8
#define R_  (T_*B_)   // 16384 rows

// ---------------- scratch -------------------------------------------------
__device__ __align__(16) float g_xn [(size_t)R_*D_];   // tf32-rounded
__device__ __align__(16) float g_xtn[(size_t)R_*D_];   // tf32-rounded
__device__ __align__(16) float g_q  [(size_t)R_*D_];
__device__ __align__(16) float g_k  [(size_t)R_*D_];
__device__ __align__(16) float g_v  [(size_t)R_*D_];
__device__ __align__(16) unsigned g_wc[3u*1024*1024];  // tf32-rounded weights
__device__ __align__(16) float g_pmax[32*B_*D_];
__device__ __align__(16) float g_psum[32*B_*D_];
__device__ __align__(16) float g_cmax[B_*D_];
__device__ __align__(16) float g_csum[B_*D_];
__device__ __align__(16) float g_attp[16ull*32*16384];  // [split][bh][l][d]
__device__ __align__(16) float g_att [(size_t)32*16384]; // [bh][l][d], tf32-rounded

// ---------------- helpers -------------------------------------------------
__device__ __forceinline__ unsigned f2t(float f) {
    unsigned u; asm("cvt.rna.tf32.f32 %0, %1;" : "=r"(u) : "f"(f)); return u;
}
// swizzled [128][32] u32 tile: element (row, col) -> row*32 + ((g^ (row&7))<<2) + e
__device__ __forceinline__ unsigned lds1(const unsigned* base, int row, int col) {
    int g = col >> 2, e = col & 3;
    return base[row*32 + (((g ^ (row & 7)) << 2) | e)];
}
__device__ __forceinline__ void cp_async16(void* smem, const void* gmem) {
    unsigned sa = (unsigned)__cvta_generic_to_shared(smem);
    asm volatile("cp.async.cg.shared.global [%0], [%1], 16;\n" :: "r"(sa), "l"(gmem));
}
#define CP_COMMIT()  asm volatile("cp.async.commit_group;\n")
#define CP_WAIT(n)   asm volatile("cp.async.wait_group %0;\n" :: "n"(n))

__device__ __forceinline__ void mma8(float* d, const unsigned* a, const unsigned* b) {
    asm volatile(
        "mma.sync.aligned.m16n8k8.row.col.f32.tf32.tf32.f32 "
        "{%0,%1,%2,%3}, {%4,%5,%6,%7}, {%8,%9}, {%0,%1,%2,%3};"
        : "+f"(d[0]), "+f"(d[1]), "+f"(d[2]), "+f"(d[3])
        : "r"(a[0]), "r"(a[1]), "r"(a[2]), "r"(a[3]), "r"(b[0]), "r"(b[1]));
}

// ---------------- weight pre-round to tf32 --------------------------------
__global__ void cvt_w(const float* __restrict__ w0, const float* __restrict__ w1,
                      const float* __restrict__ w2) {
    int i4 = blockIdx.x*256 + threadIdx.x;        // 3*262144 float4s
    int which = i4 >> 18;
    int off = i4 & 262143;
    const float* s = (which == 0) ? w0 : (which == 1 ? w1 : w2);
    float4 v = *(const float4*)(s + (size_t)off*4);
    uint4 o = make_uint4(f2t(v.x), f2t(v.y), f2t(v.z), f2t(v.w));
    *(uint4*)(g_wc + (size_t)which*1048576 + (size_t)off*4) = o;
}

// ---------------- LayerNorm (both branches, outputs tf32-rounded) ----------
__global__ void ln_kernel(const float* __restrict__ x,
                          const float* __restrict__ nw, const float* __restrict__ nb,
                          const float* __restrict__ tw, const float* __restrict__ tb) {
    int rin = blockIdx.x;            // t*B + b
    int t = rin / B_, b = rin % B_;
    const float* xr = x + (size_t)rin * D_;
    int tid = threadIdx.x;

    float v[4];
    float s = 0.f, s2 = 0.f;
#pragma unroll
    for (int j = 0; j < 4; j++) {
        v[j] = xr[tid + j*256];
        s  += v[j];
        s2 += v[j]*v[j];
    }
    __shared__ float red[40];
#pragma unroll
    for (int o = 16; o; o >>= 1) {
        s  += __shfl_xor_sync(0xffffffffu, s,  o);
        s2 += __shfl_xor_sync(0xffffffffu, s2, o);
    }
    if ((tid & 31) == 0) { red[tid>>5] = s; red[8 + (tid>>5)] = s2; }
    __syncthreads();
    if (tid < 32) {
        float a = (tid < 8) ? red[tid]     : 0.f;
        float c = (tid < 8) ? red[8 + tid] : 0.f;
#pragma unroll
        for (int o = 4; o; o >>= 1) {
            a += __shfl_xor_sync(0xffffffffu, a, o);
            c += __shfl_xor_sync(0xffffffffu, c, o);
        }
        if (tid == 0) { red[32] = a; red[33] = c; }
    }
    __syncthreads();
    float mean = red[32] * (1.f / D_);
    float var  = red[33] * (1.f / D_) - mean*mean;
    float rstd = rsqrtf(var + 1e-5f);

    size_t ro = ((size_t)b*T_ + t) * D_;
#pragma unroll
    for (int j = 0; j < 4; j++) {
        int d = tid + j*256;
        float z = (v[j] - mean) * rstd;
        g_xn [ro + d] = __uint_as_float(f2t(z * nw[d] + nb[d]));
        g_xtn[ro + d] = __uint_as_float(f2t(z * tw[d] + tb[d]));
    }
}

// ---------------- tf32 GEMM, 3-stage cp.async pipeline --------------------
__global__ void __launch_bounds__(256)
gemm_tf32(int mode, const float* __restrict__ bias) {
    extern __shared__ unsigned smg[];   // 3 stages x (As 4096 | Bs 4096)
    const float* A = (mode == 0) ? g_xn : g_xtn;
    const float* W = (const float*)(g_wc + (size_t)mode*1048576);
    float*       C = (mode == 0) ? g_q : (mode == 1 ? g_k : g_v);

    int tid  = threadIdx.x;
    int lane = tid & 31, wid = tid >> 5;
    int wm = wid >> 2, wn = wid & 3;
    int grp = lane >> 2, tg = lane & 3;
    int bm = blockIdx.y * 128, bn = blockIdx.x * 128;

    int gld = tid & 7;           // group 0..7
    int rbs = tid >> 3;          // row base 0..31

    float acc[4][4][4];
#pragma unroll
    for (int i = 0; i < 4; i++)
#pragma unroll
        for (int j = 0; j < 4; j++)
#pragma unroll
            for (int q = 0; q < 4; q++) acc[i][j][q] = 0.f;

#define GEMM_LOAD(S, K0)                                                          \
    {                                                                             \
        unsigned* As_ = smg + (S)*8192;                                           \
        unsigned* Bs_ = As_ + 4096;                                               \
        _Pragma("unroll")                                                         \
        for (int i = 0; i < 4; i++) {                                             \
            int row = rbs + i*32;                                                 \
            unsigned ph = row*32 + (((gld ^ (row & 7)) << 2));                    \
            cp_async16(&As_[ph], A + (size_t)(bm + row)*1024 + (K0) + gld*4);     \
            cp_async16(&Bs_[ph], W + (size_t)(bn + row)*1024 + (K0) + gld*4);     \
        }                                                                         \
        CP_COMMIT();                                                              \
    }

    GEMM_LOAD(0, 0)
    GEMM_LOAD(1, 32)

    for (int c = 0; c < 32; c++) {
        CP_WAIT(1);
        __syncthreads();
        const unsigned* As = smg + (c % 3)*8192;
        const unsigned* Bs = As + 4096;
#pragma unroll
        for (int kk = 0; kk < 4; kk++) {
            unsigned a[4][4], bb[4][2];
#pragma unroll
            for (int mi = 0; mi < 4; mi++) {
                int r0 = wm*64 + mi*16 + grp;
                a[mi][0] = lds1(As, r0,     kk*8 + tg);
                a[mi][1] = lds1(As, r0 + 8, kk*8 + tg);
                a[mi][2] = lds1(As, r0,     kk*8 + tg + 4);
                a[mi][3] = lds1(As, r0 + 8, kk*8 + tg + 4);
            }
#pragma unroll
            for (int ni = 0; ni < 4; ni++) {
                int c0 = wn*32 + ni*8 + grp;
                bb[ni][0] = lds1(Bs, c0, kk*8 + tg);
                bb[ni][1] = lds1(Bs, c0, kk*8 + tg + 4);
            }
#pragma unroll
            for (int mi = 0; mi < 4; mi++)
#pragma unroll
                for (int ni = 0; ni < 4; ni++)
                    mma8(acc[mi][ni], a[mi], bb[ni]);
        }
        if (c < 30) { GEMM_LOAD((c + 2) % 3, (c + 2) * 32) }
        else CP_COMMIT();
    }

#pragma unroll
    for (int mi = 0; mi < 4; mi++)
#pragma unroll
        for (int ni = 0; ni < 4; ni++) {
            int row = bm + wm*64 + mi*16 + grp;
            int col = bn + wn*32 + ni*8 + tg*2;
            float b0 = bias[col], b1 = bias[col + 1];
            C[(size_t)row*1024 + col    ] = acc[mi][ni][0] + b0;
            C[(size_t)row*1024 + col + 1] = acc[mi][ni][1] + b1;
            C[(size_t)(row+8)*1024 + col    ] = acc[mi][ni][2] + b0;
            C[(size_t)(row+8)*1024 + col + 1] = acc[mi][ni][3] + b1;
        }
#undef GEMM_LOAD
}

// ---------------- k time-softmax stats (32 splits over T) ------------------
__global__ void kstats_part() {
    int cidx = blockIdx.x*256 + threadIdx.x;   // 0..B*D-1
    int sp = blockIdx.y;                       // 0..31
    int b = cidx >> 10, dd = cidx & 1023;
    const float* base = g_k + ((size_t)(b*T_ + sp*128))*D_ + dd;
    float m = -1e30f, s = 0.f;
    for (int t = 0; t < 128; t++) {
        float val = base[(size_t)t * D_];
        float nm = fmaxf(m, val);
        s = s * __expf(m - nm) + __expf(val - nm);
        m = nm;
    }
    g_pmax[sp*(B_*D_) + cidx] = m;
    g_psum[sp*(B_*D_) + cidx] = s;
}

__global__ void kstats_combine() {
    int cidx = blockIdx.x*256 + threadIdx.x;
    float m = -1e30f;
#pragma unroll
    for (int sp = 0; sp < 32; sp++) m = fmaxf(m, g_pmax[sp*(B_*D_) + cidx]);
    float s = 0.f;
#pragma unroll
    for (int sp = 0; sp < 32; sp++)
        s += g_psum[sp*(B_*D_) + cidx] * __expf(g_pmax[sp*(B_*D_) + cidx] - m);
    g_cmax[cidx] = m;
    g_csum[cidx] = s;
}

// ---------------- stage5: attp[l][d] += v[t][l]*exp(k[t][d]-cmax), tf32 mma -
__global__ void __launch_bounds__(256) stage5_partial() {
    int bh = blockIdx.x;               // 0..31
    int b = bh >> 3, h = bh & 7;
    int sp = blockIdx.y;               // 0..15 (256 t each)

    __shared__ __align__(16) unsigned vsT[128*32];  // A: rows = l, cols = t
    __shared__ __align__(16) unsigned ksT[128*32];  // B: rows = d, cols = t

    int tid = threadIdx.x;
    int lane = tid & 31, wid = tid >> 5;
    int wm = wid >> 2, wn = wid & 3;
    int grp = lane >> 2, tg = lane & 3;

    int col = tid & 127;               // feature index (both l and d roles)
    int tq  = tid >> 7;                // 0..1
    float cm = g_cmax[b*D_ + h*128 + col];

    float acc[4][4][4];
#pragma unroll
    for (int i = 0; i < 4; i++)
#pragma unroll
        for (int j = 0; j < 4; j++)
#pragma unroll
            for (int q = 0; q < 4; q++) acc[i][j][q] = 0.f;

    for (int c = 0; c < 8; c++) {
        int t0 = sp*256 + c*32;
        __syncthreads();
#pragma unroll
        for (int i = 0; i < 4; i++) {
            int tg4 = tq + i*2;        // 0..7 t-groups of 4
            float kv[4], vv[4];
#pragma unroll
            for (int j = 0; j < 4; j++) {
                size_t off = ((size_t)(b*T_ + t0 + tg4*4 + j))*D_ + h*128 + col;
                kv[j] = __expf(g_k[off] - cm);
                vv[j] = g_v[off];
            }
            unsigned ph = col*32 + (((tg4 ^ (col & 7)) << 2));
            *(uint4*)&ksT[ph] = make_uint4(f2t(kv[0]), f2t(kv[1]), f2t(kv[2]), f2t(kv[3]));
            *(uint4*)&vsT[ph] = make_uint4(f2t(vv[0]), f2t(vv[1]), f2t(vv[2]), f2t(vv[3]));
        }
        __syncthreads();
#pragma unroll
        for (int kk = 0; kk < 4; kk++) {
            unsigned a[4][4], bb[4][2];
#pragma unroll
            for (int mi = 0; mi < 4; mi++) {
                int r0 = wm*64 + mi*16 + grp;
                a[mi][0] = lds1(vsT, r0,     kk*8 + tg);
                a[mi][1] = lds1(vsT, r0 + 8, kk*8 + tg);
                a[mi][2] = lds1(vsT, r0,     kk*8 + tg + 4);
                a[mi][3] = lds1(vsT, r0 + 8, kk*8 + tg + 4);
            }
#pragma unroll
            for (int ni = 0; ni < 4; ni++) {
                int c0 = wn*32 + ni*8 + grp;
                bb[ni][0] = lds1(ksT, c0, kk*8 + tg);
                bb[ni][1] = lds1(ksT, c0, kk*8 + tg + 4);
            }
#pragma unroll
            for (int mi = 0; mi < 4; mi++)
#pragma unroll
                for (int ni = 0; ni < 4; ni++)
                    mma8(acc[mi][ni], a[mi], bb[ni]);
        }
    }

    float* outp = g_attp + ((size_t)(sp*32 + bh))*16384;   // [l][d]
#pragma unroll
    for (int mi = 0; mi < 4; mi++)
#pragma unroll
        for (int ni = 0; ni < 4; ni++) {
            int row = wm*64 + mi*16 + grp;      // l
            int cc  = wn*32 + ni*8 + tg*2;      // d
            outp[row*128 + cc    ] = acc[mi][ni][0];
            outp[row*128 + cc + 1] = acc[mi][ni][1];
            outp[(row+8)*128 + cc    ] = acc[mi][ni][2];
            outp[(row+8)*128 + cc + 1] = acc[mi][ni][3];
        }
}

// ---------------- reduce splits + divide by csum, output tf32-rounded ------
__global__ void stage5_reduce() {
    int idx = blockIdx.x*256 + threadIdx.x;    // 0..32*16384-1
    int bh = idx >> 14;
    int rem = idx & 16383;                      // l*128 + d
    int dd = rem & 127;
    int b = bh >> 3, h = bh & 7;
    float s = 0.f;
#pragma unroll
    for (int sp = 0; sp < 16; sp++) s += g_attp[((size_t)(sp*32 + bh))*16384 + rem];
    g_att[(size_t)bh*16384 + rem] = __uint_as_float(f2t(s / g_csum[b*D_ + h*128 + dd]));
}

// ---------------- stage6: y = softmax_hd(q) @ att, tf32 mma ----------------
__global__ void __launch_bounds__(256) stage6(float* __restrict__ out) {
    extern __shared__ unsigned sm6[];
    unsigned* qs   = sm6;           // 4 chunks x [128][32] swizzled (rows = q row)
    unsigned* attB = sm6 + 4*4096;  // 4 chunks x [128][32] swizzled (rows = l, cols = d)

    int rb = blockIdx.x;            // 128 row-blocks of 128
    int h  = blockIdx.y;
    int r0 = rb * 128;
    int b  = r0 >> 12;              // / T_
    const float* attm = g_att + ((size_t)(b*8 + h))*16384;

    int tid = threadIdx.x;
    int lane = tid & 31, wid = tid >> 5;
    int wm = wid >> 2, wn = wid & 3;
    int grp = lane >> 2, tg = lane & 3;

    // async-load att tile (already tf32-rounded)
#pragma unroll
    for (int i = 0; i < 16; i++) {
        int idx = tid + i*256;               // 4096 16B-groups
        int c = idx >> 10;
        int row = (idx >> 3) & 127;
        int g = idx & 7;
        cp_async16(&attB[c*4096 + row*32 + (((g ^ (row & 7)) << 2))],
                   attm + row*128 + c*32 + g*4);
    }
    CP_COMMIT();

    // q softmax: each warp handles 16 rows
    for (int rr = 0; rr < 16; rr++) {
        int r = wid*16 + rr;
        const float* qrow = g_q + (size_t)(r0 + r)*D_ + h*128;
        float e[4];
        float mx = -1e30f;
#pragma unroll
        for (int j = 0; j < 4; j++) { e[j] = qrow[lane + 32*j]; mx = fmaxf(mx, e[j]); }
#pragma unroll
        for (int o = 16; o; o >>= 1) mx = fmaxf(mx, __shfl_xor_sync(0xffffffffu, mx, o));
        float sm = 0.f;
#pragma unroll
        for (int j = 0; j < 4; j++) { e[j] = __expf(e[j] - mx); sm += e[j]; }
#pragma unroll
        for (int o = 16; o; o >>= 1) sm += __shfl_xor_sync(0xffffffffu, sm, o);
        float inv = 1.f / sm;
#pragma unroll
        for (int j = 0; j < 4; j++) {
            // chunk j, within-chunk col = lane
            qs[j*4096 + r*32 + ((((lane >> 2) ^ (r & 7)) << 2) | (lane & 3))] =
                f2t(e[j] * inv);
        }
    }
    CP_WAIT(0);
    __syncthreads();

    float acc[4][4][4];
#pragma unroll
    for (int i = 0; i < 4; i++)
#pragma unroll
        for (int j = 0; j < 4; j++)
#pragma unroll
            for (int q = 0; q < 4; q++) acc[i][j][q] = 0.f;

#pragma unroll
    for (int c = 0; c < 4; c++) {
        const unsigned* As = qs + c*4096;
        const unsigned* Bs = attB + c*4096;
#pragma unroll
        for (int kk = 0; kk < 4; kk++) {
            unsigned a[4][4], bb[4][2];
#pragma unroll
            for (int mi = 0; mi < 4; mi++) {
                int rr0 = wm*64 + mi*16 + grp;
                a[mi][0] = lds1(As, rr0,     kk*8 + tg);
                a[mi][1] = lds1(As, rr0 + 8, kk*8 + tg);
                a[mi][2] = lds1(As, rr0,     kk*8 + tg + 4);
                a[mi][3] = lds1(As, rr0 + 8, kk*8 + tg + 4);
            }
#pragma unroll
            for (int ni = 0; ni < 4; ni++) {
                int c0 = wn*32 + ni*8 + grp;
                bb[ni][0] = lds1(Bs, c0, kk*8 + tg);
                bb[ni][1] = lds1(Bs, c0, kk*8 + tg + 4);
            }
#pragma unroll
            for (int mi = 0; mi < 4; mi++)
#pragma unroll
                for (int ni = 0; ni < 4; ni++)
                    mma8(acc[mi][ni], a[mi], bb[ni]);
        }
    }

#pragma unroll
    for (int mi = 0; mi < 4; mi++)
#pragma unroll
        for (int ni = 0; ni < 4; ni++) {
            int row = r0 + wm*64 + mi*16 + grp;
            int cc  = h*128 + wn*32 + ni*8 + tg*2;
            out[(size_t)row*D_ + cc    ] = acc[mi][ni][0];
            out[(size_t)row*D_ + cc + 1] = acc[mi][ni][1];
            out[(size_t)(row+8)*D_ + cc    ] = acc[mi][ni][2];
            out[(size_t)(row+8)*D_ + cc + 1] = acc[mi][ni][3];
        }
}

// ---------------------------------------------------------------------------
extern "C" void kernel_launch(void* const* d_in, const int* in_sizes, int n_in,
                              void* d_out, int out_size) {
    const float* x  = (const float*)d_in[0];
    const float* nw = (const float*)d_in[1];
    const float* nb = (const float*)d_in[2];
    const float* tw = (const float*)d_in[3];
    const float* tb = (const float*)d_in[4];
    const float* Wq = (const float*)d_in[5];
    const float* bq = (const float*)d_in[6];
    const float* Wk = (const float*)d_in[7];
    const float* bk = (const float*)d_in[8];
    const float* Wv = (const float*)d_in[9];
    const float* bv = (const float*)d_in[10];
    float* out = (float*)d_out;

    cudaFuncSetAttribute(gemm_tf32, cudaFuncAttributeMaxDynamicSharedMemorySize, 98304);
    cudaFuncSetAttribute(stage6,    cudaFuncAttributeMaxDynamicSharedMemorySize, 131072);

    cvt_w<<<3072, 256>>>(Wq, Wk, Wv);
    ln_kernel<<<R_, 256>>>(x, nw, nb, tw, tb);

    dim3 gg(D_/128, R_/128);                       // (8, 128)
    gemm_tf32<<<gg, 256, 98304>>>(0, bq);
    gemm_tf32<<<gg, 256, 98304>>>(1, bk);
    gemm_tf32<<<gg, 256, 98304>>>(2, bv);

    kstats_part<<<dim3((B_*D_)/256, 32), 256>>>();
    kstats_combine<<<(B_*D_)/256, 256>>>();

    stage5_partial<<<dim3(32, 16), 256>>>();
    stage5_reduce<<<(32*16384)/256, 256>>>();      // 2048 blocks

    stage6<<<dim3(128, 8), 256, 131072>>>(out);
}

// round 4
// speedup vs baseline: 2.3225x; 1.6746x over previous
#include <cuda_runtime.h>
#include <cuda_fp16.h>
#include <cstdint>

#define T_  4096
#define B_  4
#define D_  1024
#define H_  8
#define R_  (T_*B_)   // 16384 rows

// ---------------- scratch -------------------------------------------------
__device__ __align__(16) __half g_xn [(size_t)R_*D_];   // fp16 LN outputs
__device__ __align__(16) __half g_xtn[(size_t)R_*D_];
__device__ __align__(16) float g_q  [(size_t)R_*D_];
__device__ __align__(16) float g_k  [(size_t)R_*D_];
__device__ __align__(16) float g_v  [(size_t)R_*D_];
__device__ __align__(16) __half g_wh[3u*1024*1024];     // fp16 weights
__device__ __align__(16) float g_pmax[32*B_*D_];
__device__ __align__(16) float g_psum[32*B_*D_];
__device__ __align__(16) float g_cmax[B_*D_];
__device__ __align__(16) float g_csum[B_*D_];
__device__ __align__(16) float g_attp[16ull*32*16384];  // [split][bh][l][d]
__device__ __align__(16) float g_att [(size_t)32*16384]; // [bh][l][d], tf32-rounded

// ---------------- helpers -------------------------------------------------
__device__ __forceinline__ unsigned f2t(float f) {
    unsigned u; asm("cvt.rna.tf32.f32 %0, %1;" : "=r"(u) : "f"(f)); return u;
}
__device__ __forceinline__ unsigned lds1(const unsigned* base, int row, int col) {
    int g = col >> 2, e = col & 3;
    return base[row*32 + (((g ^ (row & 7)) << 2) | e)];
}
__device__ __forceinline__ void cp_async16(void* smem, const void* gmem) {
    unsigned sa = (unsigned)__cvta_generic_to_shared(smem);
    asm volatile("cp.async.cg.shared.global [%0], [%1], 16;\n" :: "r"(sa), "l"(gmem));
}
#define CP_COMMIT()  asm volatile("cp.async.commit_group;\n")
#define CP_WAIT(n)   asm volatile("cp.async.wait_group %0;\n" :: "n"(n))

// legacy tf32 mma (stage5/stage6)
__device__ __forceinline__ void mma8(float* d, const unsigned* a, const unsigned* b) {
    asm volatile(
        "mma.sync.aligned.m16n8k8.row.col.f32.tf32.tf32.f32 "
        "{%0,%1,%2,%3}, {%4,%5,%6,%7}, {%8,%9}, {%0,%1,%2,%3};"
        : "+f"(d[0]), "+f"(d[1]), "+f"(d[2]), "+f"(d[3])
        : "r"(a[0]), "r"(a[1]), "r"(a[2]), "r"(a[3]), "r"(b[0]), "r"(b[1]));
}
// fp16 mma m16n8k16
__device__ __forceinline__ void mma16(float* d, const uint32_t* a, const uint32_t* b) {
    asm volatile(
        "mma.sync.aligned.m16n8k16.row.col.f32.f16.f16.f32 "
        "{%0,%1,%2,%3}, {%4,%5,%6,%7}, {%8,%9}, {%0,%1,%2,%3};"
        : "+f"(d[0]), "+f"(d[1]), "+f"(d[2]), "+f"(d[3])
        : "r"(a[0]), "r"(a[1]), "r"(a[2]), "r"(a[3]), "r"(b[0]), "r"(b[1]));
}
__device__ __forceinline__ void ldsm4(uint32_t* r, uint32_t addr) {
    asm volatile("ldmatrix.sync.aligned.m8n8.x4.shared.b16 {%0,%1,%2,%3}, [%4];"
        : "=r"(r[0]), "=r"(r[1]), "=r"(r[2]), "=r"(r[3]) : "r"(addr));
}

// ---------------- weight convert to fp16 ------------------------------------
__global__ void cvt_w(const float* __restrict__ w0, const float* __restrict__ w1,
                      const float* __restrict__ w2) {
    int i4 = blockIdx.x*256 + threadIdx.x;        // 3*262144 float4s
    int which = i4 >> 18;
    int off = i4 & 262143;
    const float* s = (which == 0) ? w0 : (which == 1 ? w1 : w2);
    float4 v = *(const float4*)(s + (size_t)off*4);
    __half2 h0 = __floats2half2_rn(v.x, v.y);
    __half2 h1 = __floats2half2_rn(v.z, v.w);
    *(uint2*)(g_wh + (size_t)which*1048576 + (size_t)off*4) =
        make_uint2(*(unsigned*)&h0, *(unsigned*)&h1);
}

// ---------------- LayerNorm (both branches, outputs fp16) ------------------
__global__ void ln_kernel(const float* __restrict__ x,
                          const float* __restrict__ nw, const float* __restrict__ nb,
                          const float* __restrict__ tw, const float* __restrict__ tb) {
    int rin = blockIdx.x;            // t*B + b
    int t = rin / B_, b = rin % B_;
    const float* xr = x + (size_t)rin * D_;
    int tid = threadIdx.x;

    float v[4];
    float s = 0.f, s2 = 0.f;
#pragma unroll
    for (int j = 0; j < 4; j++) {
        v[j] = xr[tid + j*256];
        s  += v[j];
        s2 += v[j]*v[j];
    }
    __shared__ float red[40];
#pragma unroll
    for (int o = 16; o; o >>= 1) {
        s  += __shfl_xor_sync(0xffffffffu, s,  o);
        s2 += __shfl_xor_sync(0xffffffffu, s2, o);
    }
    if ((tid & 31) == 0) { red[tid>>5] = s; red[8 + (tid>>5)] = s2; }
    __syncthreads();
    if (tid < 32) {
        float a = (tid < 8) ? red[tid]     : 0.f;
        float c = (tid < 8) ? red[8 + tid] : 0.f;
#pragma unroll
        for (int o = 4; o; o >>= 1) {
            a += __shfl_xor_sync(0xffffffffu, a, o);
            c += __shfl_xor_sync(0xffffffffu, c, o);
        }
        if (tid == 0) { red[32] = a; red[33] = c; }
    }
    __syncthreads();
    float mean = red[32] * (1.f / D_);
    float var  = red[33] * (1.f / D_) - mean*mean;
    float rstd = rsqrtf(var + 1e-5f);

    size_t ro = ((size_t)b*T_ + t) * D_;
#pragma unroll
    for (int j = 0; j < 4; j++) {
        int d = tid + j*256;
        float z = (v[j] - mean) * rstd;
        g_xn [ro + d] = __float2half_rn(z * nw[d] + nb[d]);
        g_xtn[ro + d] = __float2half_rn(z * tw[d] + tb[d]);
    }
}

// ---------------- fp16 GEMM: C = A @ W^T + bias  (128x128 tile, k-chunk 64) -
// 3-stage cp.async, ldmatrix fragments, 8 warps (4 x 2), warp tile 32x64.
__global__ void __launch_bounds__(256, 2)
gemm_f16(const float* __restrict__ bq, const float* __restrict__ bk,
         const float* __restrict__ bv) {
    extern __shared__ char smraw[];
    uint32_t sbase = (uint32_t)__cvta_generic_to_shared(smraw);
    int mode = blockIdx.z;
    const __half* A = (mode == 0) ? g_xn : g_xtn;
    const __half* W = g_wh + (size_t)mode*1048576;
    float*        C = (mode == 0) ? g_q : (mode == 1 ? g_k : g_v);
    const float*  bias = (mode == 0) ? bq : (mode == 1 ? bk : bv);

    int tid = threadIdx.x;
    int lane = tid & 31, wid = tid >> 5;
    int wm = wid & 3, wn = wid >> 2;      // rows: wm*32, cols: wn*64
    int bm = blockIdx.y * 128, bn = blockIdx.x * 128;

    int q = lane >> 3, r = lane & 7;
    int grp = lane >> 2, tg = lane & 3;

    float acc[2][8][4];
#pragma unroll
    for (int i = 0; i < 2; i++)
#pragma unroll
        for (int j = 0; j < 8; j++)
#pragma unroll
            for (int e = 0; e < 4; e++) acc[i][j][e] = 0.f;

    // stage s: A at s*32768, B at s*32768 + 16384 (rows of 128B = 64 halves)
#define LOAD_CHUNK(S, KC)                                                        \
    {                                                                            \
        char* As_ = smraw + (S)*32768;                                           \
        char* Bs_ = As_ + 16384;                                                 \
        _Pragma("unroll")                                                        \
        for (int i = 0; i < 4; i++) {                                            \
            int idx = tid + i*256;                                               \
            int rr = idx >> 3, g = idx & 7;                                      \
            cp_async16(As_ + rr*128 + ((g ^ (rr & 7)) << 4),                     \
                       A + (size_t)(bm + rr)*1024 + (KC)*64 + g*8);              \
            cp_async16(Bs_ + rr*128 + ((g ^ (rr & 7)) << 4),                     \
                       W + (size_t)(bn + rr)*1024 + (KC)*64 + g*8);              \
        }                                                                        \
        CP_COMMIT();                                                             \
    }

    LOAD_CHUNK(0, 0)
    LOAD_CHUNK(1, 1)

    for (int c = 0; c < 16; c++) {
        if (c < 15) { CP_WAIT(1); } else { CP_WAIT(0); }
        __syncthreads();
        uint32_t Asm = sbase + (c % 3)*32768;
        uint32_t Bsm = Asm + 16384;

#pragma unroll
        for (int ks = 0; ks < 4; ks++) {
            uint32_t a[2][4], bfr[4][4];
#pragma unroll
            for (int mi = 0; mi < 2; mi++) {
                int row = wm*32 + mi*16 + r + ((q & 1) << 3);
                int kh  = ks*16 + ((q >> 1) << 3);
                ldsm4(a[mi], Asm + row*128 + (((kh >> 3) ^ (row & 7)) << 4));
            }
#pragma unroll
            for (int nj = 0; nj < 4; nj++) {
                int nrow = wn*64 + nj*16 + r + ((q >> 1) << 3);
                int kh   = ks*16 + ((q & 1) << 3);
                ldsm4(bfr[nj], Bsm + nrow*128 + (((kh >> 3) ^ (nrow & 7)) << 4));
            }
#pragma unroll
            for (int mi = 0; mi < 2; mi++)
#pragma unroll
                for (int nj = 0; nj < 4; nj++) {
                    mma16(acc[mi][nj*2 + 0], a[mi], &bfr[nj][0]);
                    mma16(acc[mi][nj*2 + 1], a[mi], &bfr[nj][2]);
                }
        }
        __syncthreads();
        if (c + 2 < 16) { LOAD_CHUNK((c & 1) ? ((c + 2) % 3) : ((c + 2) % 3), c + 2) }
    }
#undef LOAD_CHUNK

    // epilogue
#pragma unroll
    for (int mi = 0; mi < 2; mi++)
#pragma unroll
        for (int ni = 0; ni < 8; ni++) {
            int row = bm + wm*32 + mi*16 + grp;
            int col = bn + wn*64 + ni*8 + tg*2;
            float b0 = bias[col], b1 = bias[col + 1];
            *(float2*)(C + (size_t)row*1024 + col) =
                make_float2(acc[mi][ni][0] + b0, acc[mi][ni][1] + b1);
            *(float2*)(C + (size_t)(row + 8)*1024 + col) =
                make_float2(acc[mi][ni][2] + b0, acc[mi][ni][3] + b1);
        }
}

// ---------------- k time-softmax stats (32 splits over T) ------------------
__global__ void kstats_part() {
    int cidx = blockIdx.x*256 + threadIdx.x;   // 0..B*D-1
    int sp = blockIdx.y;                       // 0..31
    int b = cidx >> 10;
    const float* base = g_k + ((size_t)(b*T_ + sp*128))*D_ + (cidx & 1023);
    float m = -1e30f, s = 0.f;
    for (int t = 0; t < 128; t++) {
        float val = base[(size_t)t * D_];
        float nm = fmaxf(m, val);
        s = s * __expf(m - nm) + __expf(val - nm);
        m = nm;
    }
    g_pmax[sp*(B_*D_) + cidx] = m;
    g_psum[sp*(B_*D_) + cidx] = s;
}

__global__ void kstats_combine() {
    int cidx = blockIdx.x*256 + threadIdx.x;
    float m = -1e30f;
#pragma unroll
    for (int sp = 0; sp < 32; sp++) m = fmaxf(m, g_pmax[sp*(B_*D_) + cidx]);
    float s = 0.f;
#pragma unroll
    for (int sp = 0; sp < 32; sp++)
        s += g_psum[sp*(B_*D_) + cidx] * __expf(g_pmax[sp*(B_*D_) + cidx] - m);
    g_cmax[cidx] = m;
    g_csum[cidx] = s;
}

// ---------------- stage5: attp[l][d] += v[t][l]*exp(k[t][d]-cmax), mma.sync -
__global__ void __launch_bounds__(256) stage5_partial() {
    int bh = blockIdx.x;
    int b = bh >> 3, h = bh & 7;
    int sp = blockIdx.y;               // 0..15 (256 t each)

    __shared__ __align__(16) unsigned vsT[128*32];  // A: rows = l, cols = t
    __shared__ __align__(16) unsigned ksT[128*32];  // B: rows = d, cols = t

    int tid = threadIdx.x;
    int lane = tid & 31, wid = tid >> 5;
    int wm = wid >> 2, wn = wid & 3;
    int grp = lane >> 2, tg = lane & 3;

    int col = tid & 127;
    int tq  = tid >> 7;
    float cm = g_cmax[b*D_ + h*128 + col];

    float acc[4][4][4];
#pragma unroll
    for (int i = 0; i < 4; i++)
#pragma unroll
        for (int j = 0; j < 4; j++)
#pragma unroll
            for (int e = 0; e < 4; e++) acc[i][j][e] = 0.f;

    for (int c = 0; c < 8; c++) {
        int t0 = sp*256 + c*32;
        __syncthreads();
#pragma unroll
        for (int i = 0; i < 4; i++) {
            int tg4 = tq + i*2;
            float kv[4], vv[4];
#pragma unroll
            for (int j = 0; j < 4; j++) {
                size_t off = ((size_t)(b*T_ + t0 + tg4*4 + j))*D_ + h*128 + col;
                kv[j] = __expf(g_k[off] - cm);
                vv[j] = g_v[off];
            }
            unsigned ph = col*32 + (((tg4 ^ (col & 7)) << 2));
            *(uint4*)&ksT[ph] = make_uint4(f2t(kv[0]), f2t(kv[1]), f2t(kv[2]), f2t(kv[3]));
            *(uint4*)&vsT[ph] = make_uint4(f2t(vv[0]), f2t(vv[1]), f2t(vv[2]), f2t(vv[3]));
        }
        __syncthreads();
#pragma unroll
        for (int kk = 0; kk < 4; kk++) {
            unsigned a[4][4], bb[4][2];
#pragma unroll
            for (int mi = 0; mi < 4; mi++) {
                int r0 = wm*64 + mi*16 + grp;
                a[mi][0] = lds1(vsT, r0,     kk*8 + tg);
                a[mi][1] = lds1(vsT, r0 + 8, kk*8 + tg);
                a[mi][2] = lds1(vsT, r0,     kk*8 + tg + 4);
                a[mi][3] = lds1(vsT, r0 + 8, kk*8 + tg + 4);
            }
#pragma unroll
            for (int ni = 0; ni < 4; ni++) {
                int c0 = wn*32 + ni*8 + grp;
                bb[ni][0] = lds1(ksT, c0, kk*8 + tg);
                bb[ni][1] = lds1(ksT, c0, kk*8 + tg + 4);
            }
#pragma unroll
            for (int mi = 0; mi < 4; mi++)
#pragma unroll
                for (int ni = 0; ni < 4; ni++)
                    mma8(acc[mi][ni], a[mi], bb[ni]);
        }
    }

    float* outp = g_attp + ((size_t)(sp*32 + bh))*16384;   // [l][d]
#pragma unroll
    for (int mi = 0; mi < 4; mi++)
#pragma unroll
        for (int ni = 0; ni < 4; ni++) {
            int row = wm*64 + mi*16 + grp;
            int cc  = wn*32 + ni*8 + tg*2;
            outp[row*128 + cc    ] = acc[mi][ni][0];
            outp[row*128 + cc + 1] = acc[mi][ni][1];
            outp[(row+8)*128 + cc    ] = acc[mi][ni][2];
            outp[(row+8)*128 + cc + 1] = acc[mi][ni][3];
        }
}

// ---------------- reduce splits + divide by csum ---------------------------
__global__ void stage5_reduce() {
    int idx = blockIdx.x*256 + threadIdx.x;
    int bh = idx >> 14;
    int rem = idx & 16383;                      // l*128 + d
    int dd = rem & 127;
    int b = bh >> 3, h = bh & 7;
    float s = 0.f;
#pragma unroll
    for (int sp = 0; sp < 16; sp++) s += g_attp[((size_t)(sp*32 + bh))*16384 + rem];
    g_att[(size_t)bh*16384 + rem] = __uint_as_float(f2t(s / g_csum[b*D_ + h*128 + dd]));
}

// ---------------- stage6: y = softmax_hd(q) @ att, mma.sync ----------------
__global__ void __launch_bounds__(256) stage6(float* __restrict__ out) {
    extern __shared__ unsigned sm6[];
    unsigned* qs   = sm6;
    unsigned* attB = sm6 + 4*4096;

    int rb = blockIdx.x;
    int h  = blockIdx.y;
    int r0 = rb * 128;
    int b  = r0 >> 12;
    const float* attm = g_att + ((size_t)(b*8 + h))*16384;

    int tid = threadIdx.x;
    int lane = tid & 31, wid = tid >> 5;
    int wm = wid >> 2, wn = wid & 3;
    int grp = lane >> 2, tg = lane & 3;

#pragma unroll
    for (int i = 0; i < 16; i++) {
        int idx = tid + i*256;
        int c = idx >> 10;
        int row = (idx >> 3) & 127;
        int g = idx & 7;
        cp_async16(&attB[c*4096 + row*32 + (((g ^ (row & 7)) << 2))],
                   attm + row*128 + c*32 + g*4);
    }
    CP_COMMIT();

    for (int rr = 0; rr < 16; rr++) {
        int rl = wid*16 + rr;
        const float* qrow = g_q + (size_t)(r0 + rl)*D_ + h*128;
        float e[4];
        float mx = -1e30f;
#pragma unroll
        for (int j = 0; j < 4; j++) { e[j] = qrow[lane + 32*j]; mx = fmaxf(mx, e[j]); }
#pragma unroll
        for (int o = 16; o; o >>= 1) mx = fmaxf(mx, __shfl_xor_sync(0xffffffffu, mx, o));
        float sm = 0.f;
#pragma unroll
        for (int j = 0; j < 4; j++) { e[j] = __expf(e[j] - mx); sm += e[j]; }
#pragma unroll
        for (int o = 16; o; o >>= 1) sm += __shfl_xor_sync(0xffffffffu, sm, o);
        float inv = 1.f / sm;
#pragma unroll
        for (int j = 0; j < 4; j++) {
            qs[j*4096 + rl*32 + ((((lane >> 2) ^ (rl & 7)) << 2) | (lane & 3))] =
                f2t(e[j] * inv);
        }
    }
    CP_WAIT(0);
    __syncthreads();

    float acc[4][4][4];
#pragma unroll
    for (int i = 0; i < 4; i++)
#pragma unroll
        for (int j = 0; j < 4; j++)
#pragma unroll
            for (int e = 0; e < 4; e++) acc[i][j][e] = 0.f;

#pragma unroll
    for (int c = 0; c < 4; c++) {
        const unsigned* As = qs + c*4096;
        const unsigned* Bs = attB + c*4096;
#pragma unroll
        for (int kk = 0; kk < 4; kk++) {
            unsigned a[4][4], bb[4][2];
#pragma unroll
            for (int mi = 0; mi < 4; mi++) {
                int rr0 = wm*64 + mi*16 + grp;
                a[mi][0] = lds1(As, rr0,     kk*8 + tg);
                a[mi][1] = lds1(As, rr0 + 8, kk*8 + tg);
                a[mi][2] = lds1(As, rr0,     kk*8 + tg + 4);
                a[mi][3] = lds1(As, rr0 + 8, kk*8 + tg + 4);
            }
#pragma unroll
            for (int ni = 0; ni < 4; ni++) {
                int c0 = wn*32 + ni*8 + grp;
                bb[ni][0] = lds1(Bs, c0, kk*8 + tg);
                bb[ni][1] = lds1(Bs, c0, kk*8 + tg + 4);
            }
#pragma unroll
            for (int mi = 0; mi < 4; mi++)
#pragma unroll
                for (int ni = 0; ni < 4; ni++)
                    mma8(acc[mi][ni], a[mi], bb[ni]);
        }
    }

#pragma unroll
    for (int mi = 0; mi < 4; mi++)
#pragma unroll
        for (int ni = 0; ni < 4; ni++) {
            int row = r0 + wm*64 + mi*16 + grp;
            int cc  = h*128 + wn*32 + ni*8 + tg*2;
            out[(size_t)row*D_ + cc    ] = acc[mi][ni][0];
            out[(size_t)row*D_ + cc + 1] = acc[mi][ni][1];
            out[(size_t)(row+8)*D_ + cc    ] = acc[mi][ni][2];
            out[(size_t)(row+8)*D_ + cc + 1] = acc[mi][ni][3];
        }
}

// ---------------------------------------------------------------------------
extern "C" void kernel_launch(void* const* d_in, const int* in_sizes, int n_in,
                              void* d_out, int out_size) {
    const float* x  = (const float*)d_in[0];
    const float* nw = (const float*)d_in[1];
    const float* nb = (const float*)d_in[2];
    const float* tw = (const float*)d_in[3];
    const float* tb = (const float*)d_in[4];
    const float* Wq = (const float*)d_in[5];
    const float* bq = (const float*)d_in[6];
    const float* Wk = (const float*)d_in[7];
    const float* bk = (const float*)d_in[8];
    const float* Wv = (const float*)d_in[9];
    const float* bv = (const float*)d_in[10];
    float* out = (float*)d_out;

    cudaFuncSetAttribute(gemm_f16, cudaFuncAttributeMaxDynamicSharedMemorySize, 98304);
    cudaFuncSetAttribute(stage6,   cudaFuncAttributeMaxDynamicSharedMemorySize, 131072);

    cvt_w<<<3072, 256>>>(Wq, Wk, Wv);
    ln_kernel<<<R_, 256>>>(x, nw, nb, tw, tb);

    // fused Q/K/V projections: grid (N-tiles, M-tiles, mode)
    gemm_f16<<<dim3(8, 128, 3), 256, 98304>>>(bq, bk, bv);

    kstats_part<<<dim3((B_*D_)/256, 32), 256>>>();
    kstats_combine<<<(B_*D_)/256, 256>>>();

    stage5_partial<<<dim3(32, 16), 256>>>();
    stage5_reduce<<<(32*16384)/256, 256>>>();

    stage6<<<dim3(128, 8), 256, 131072>>>(out);
}

// round 5
// speedup vs baseline: 2.7620x; 1.1892x over previous
#include <cuda_runtime.h>
#include <cuda_fp16.h>
#include <cstdint>

#define T_  4096
#define B_  4
#define D_  1024
#define H_  8
#define R_  (T_*B_)   // 16384 rows

// ---------------- scratch -------------------------------------------------
__device__ __align__(16) __half g_xn [(size_t)R_*D_];
__device__ __align__(16) __half g_xtn[(size_t)R_*D_];
__device__ __align__(16) __half g_q  [(size_t)R_*D_];
__device__ __align__(16) __half g_k  [(size_t)R_*D_];
__device__ __align__(16) __half g_v  [(size_t)R_*D_];
__device__ __align__(16) __half g_wh[3u*1024*1024];
__device__ __align__(16) float g_pmax[32*B_*D_];
__device__ __align__(16) float g_psum[32*B_*D_];
__device__ __align__(16) float g_cmax[B_*D_];
__device__ __align__(16) float g_csum[B_*D_];
__device__ __align__(16) float g_attp[16ull*32*16384];   // [split][bh][l][d] fp32
__device__ __align__(16) __half g_att [(size_t)32*16384]; // [bh][l][d] fp16

// ---------------- helpers -------------------------------------------------
__device__ __forceinline__ void cp_async16(void* smem, const void* gmem) {
    unsigned sa = (unsigned)__cvta_generic_to_shared(smem);
    asm volatile("cp.async.cg.shared.global [%0], [%1], 16;\n" :: "r"(sa), "l"(gmem));
}
#define CP_COMMIT()  asm volatile("cp.async.commit_group;\n")
#define CP_WAIT(n)   asm volatile("cp.async.wait_group %0;\n" :: "n"(n))

__device__ __forceinline__ void mma16(float* d, const uint32_t* a, const uint32_t* b) {
    asm volatile(
        "mma.sync.aligned.m16n8k16.row.col.f32.f16.f16.f32 "
        "{%0,%1,%2,%3}, {%4,%5,%6,%7}, {%8,%9}, {%0,%1,%2,%3};"
        : "+f"(d[0]), "+f"(d[1]), "+f"(d[2]), "+f"(d[3])
        : "r"(a[0]), "r"(a[1]), "r"(a[2]), "r"(a[3]), "r"(b[0]), "r"(b[1]));
}
__device__ __forceinline__ void ldsm4(uint32_t* r, uint32_t addr) {
    asm volatile("ldmatrix.sync.aligned.m8n8.x4.shared.b16 {%0,%1,%2,%3}, [%4];"
        : "=r"(r[0]), "=r"(r[1]), "=r"(r[2]), "=r"(r[3]) : "r"(addr));
}

// ---------------- weight convert to fp16 ------------------------------------
__global__ void cvt_w(const float* __restrict__ w0, const float* __restrict__ w1,
                      const float* __restrict__ w2) {
    int i4 = blockIdx.x*256 + threadIdx.x;
    int which = i4 >> 18;
    int off = i4 & 262143;
    const float* s = (which == 0) ? w0 : (which == 1 ? w1 : w2);
    float4 v = *(const float4*)(s + (size_t)off*4);
    __half2 h0 = __floats2half2_rn(v.x, v.y);
    __half2 h1 = __floats2half2_rn(v.z, v.w);
    *(uint2*)(g_wh + (size_t)which*1048576 + (size_t)off*4) =
        make_uint2(*(unsigned*)&h0, *(unsigned*)&h1);
}

// ---------------- LayerNorm (both branches, outputs fp16) ------------------
__global__ void ln_kernel(const float* __restrict__ x,
                          const float* __restrict__ nw, const float* __restrict__ nb,
                          const float* __restrict__ tw, const float* __restrict__ tb) {
    int rin = blockIdx.x;
    int t = rin / B_, b = rin % B_;
    const float* xr = x + (size_t)rin * D_;
    int tid = threadIdx.x;

    float v[4];
    float s = 0.f, s2 = 0.f;
#pragma unroll
    for (int j = 0; j < 4; j++) {
        v[j] = xr[tid + j*256];
        s  += v[j];
        s2 += v[j]*v[j];
    }
    __shared__ float red[40];
#pragma unroll
    for (int o = 16; o; o >>= 1) {
        s  += __shfl_xor_sync(0xffffffffu, s,  o);
        s2 += __shfl_xor_sync(0xffffffffu, s2, o);
    }
    if ((tid & 31) == 0) { red[tid>>5] = s; red[8 + (tid>>5)] = s2; }
    __syncthreads();
    if (tid < 32) {
        float a = (tid < 8) ? red[tid]     : 0.f;
        float c = (tid < 8) ? red[8 + tid] : 0.f;
#pragma unroll
        for (int o = 4; o; o >>= 1) {
            a += __shfl_xor_sync(0xffffffffu, a, o);
            c += __shfl_xor_sync(0xffffffffu, c, o);
        }
        if (tid == 0) { red[32] = a; red[33] = c; }
    }
    __syncthreads();
    float mean = red[32] * (1.f / D_);
    float var  = red[33] * (1.f / D_) - mean*mean;
    float rstd = rsqrtf(var + 1e-5f);

    size_t ro = ((size_t)b*T_ + t) * D_;
#pragma unroll
    for (int j = 0; j < 4; j++) {
        int d = tid + j*256;
        float z = (v[j] - mean) * rstd;
        g_xn [ro + d] = __float2half_rn(z * nw[d] + nb[d]);
        g_xtn[ro + d] = __float2half_rn(z * tw[d] + tb[d]);
    }
}

// ---------------- fp16 GEMM: C = A @ W^T + bias (fp16 out) -----------------
__global__ void __launch_bounds__(256, 2)
gemm_f16(const float* __restrict__ bq, const float* __restrict__ bk,
         const float* __restrict__ bv) {
    extern __shared__ char smraw[];
    uint32_t sbase = (uint32_t)__cvta_generic_to_shared(smraw);
    int mode = blockIdx.z;
    const __half* A = (mode == 0) ? g_xn : g_xtn;
    const __half* W = g_wh + (size_t)mode*1048576;
    __half*       C = (mode == 0) ? g_q : (mode == 1 ? g_k : g_v);
    const float*  bias = (mode == 0) ? bq : (mode == 1 ? bk : bv);

    int tid = threadIdx.x;
    int lane = tid & 31, wid = tid >> 5;
    int wm = wid & 3, wn = wid >> 2;
    int bm = blockIdx.y * 128, bn = blockIdx.x * 128;

    int q = lane >> 3, r = lane & 7;
    int grp = lane >> 2, tg = lane & 3;

    float acc[2][8][4];
#pragma unroll
    for (int i = 0; i < 2; i++)
#pragma unroll
        for (int j = 0; j < 8; j++)
#pragma unroll
            for (int e = 0; e < 4; e++) acc[i][j][e] = 0.f;

#define LOAD_CHUNK(S, KC)                                                        \
    {                                                                            \
        char* As_ = smraw + (S)*32768;                                           \
        char* Bs_ = As_ + 16384;                                                 \
        _Pragma("unroll")                                                        \
        for (int i = 0; i < 4; i++) {                                            \
            int idx = tid + i*256;                                               \
            int rr = idx >> 3, g = idx & 7;                                      \
            cp_async16(As_ + rr*128 + ((g ^ (rr & 7)) << 4),                     \
                       A + (size_t)(bm + rr)*1024 + (KC)*64 + g*8);              \
            cp_async16(Bs_ + rr*128 + ((g ^ (rr & 7)) << 4),                     \
                       W + (size_t)(bn + rr)*1024 + (KC)*64 + g*8);              \
        }                                                                        \
        CP_COMMIT();                                                             \
    }

    LOAD_CHUNK(0, 0)
    LOAD_CHUNK(1, 1)

    for (int c = 0; c < 16; c++) {
        if (c < 15) { CP_WAIT(1); } else { CP_WAIT(0); }
        __syncthreads();
        uint32_t Asm = sbase + (c % 3)*32768;
        uint32_t Bsm = Asm + 16384;

#pragma unroll
        for (int ks = 0; ks < 4; ks++) {
            uint32_t a[2][4], bfr[4][4];
#pragma unroll
            for (int mi = 0; mi < 2; mi++) {
                int row = wm*32 + mi*16 + r + ((q & 1) << 3);
                int kh  = ks*16 + ((q >> 1) << 3);
                ldsm4(a[mi], Asm + row*128 + (((kh >> 3) ^ (row & 7)) << 4));
            }
#pragma unroll
            for (int nj = 0; nj < 4; nj++) {
                int nrow = wn*64 + nj*16 + r + ((q >> 1) << 3);
                int kh   = ks*16 + ((q & 1) << 3);
                ldsm4(bfr[nj], Bsm + nrow*128 + (((kh >> 3) ^ (nrow & 7)) << 4));
            }
#pragma unroll
            for (int mi = 0; mi < 2; mi++)
#pragma unroll
                for (int nj = 0; nj < 4; nj++) {
                    mma16(acc[mi][nj*2 + 0], a[mi], &bfr[nj][0]);
                    mma16(acc[mi][nj*2 + 1], a[mi], &bfr[nj][2]);
                }
        }
        __syncthreads();
        if (c + 2 < 16) { LOAD_CHUNK((c + 2) % 3, c + 2) }
    }
#undef LOAD_CHUNK

#pragma unroll
    for (int mi = 0; mi < 2; mi++)
#pragma unroll
        for (int ni = 0; ni < 8; ni++) {
            int row = bm + wm*32 + mi*16 + grp;
            int col = bn + wn*64 + ni*8 + tg*2;
            float b0 = bias[col], b1 = bias[col + 1];
            __half2 lo = __floats2half2_rn(acc[mi][ni][0] + b0, acc[mi][ni][1] + b1);
            __half2 hi = __floats2half2_rn(acc[mi][ni][2] + b0, acc[mi][ni][3] + b1);
            *(__half2*)(C + (size_t)row*1024 + col) = lo;
            *(__half2*)(C + (size_t)(row + 8)*1024 + col) = hi;
        }
}

// ---------------- k time-softmax stats (32 splits over T) ------------------
__global__ void kstats_part() {
    int cidx = blockIdx.x*256 + threadIdx.x;   // 0..B*D-1
    int sp = blockIdx.y;                       // 0..31
    int b = cidx >> 10;
    const __half* base = g_k + ((size_t)(b*T_ + sp*128))*D_ + (cidx & 1023);
    float m = -1e30f, s = 0.f;
    for (int t = 0; t < 128; t++) {
        float val = __half2float(base[(size_t)t * D_]);
        float nm = fmaxf(m, val);
        s = s * __expf(m - nm) + __expf(val - nm);
        m = nm;
    }
    g_pmax[sp*(B_*D_) + cidx] = m;
    g_psum[sp*(B_*D_) + cidx] = s;
}

__global__ void kstats_combine() {
    int cidx = blockIdx.x*256 + threadIdx.x;
    float m = -1e30f;
#pragma unroll
    for (int sp = 0; sp < 32; sp++) m = fmaxf(m, g_pmax[sp*(B_*D_) + cidx]);
    float s = 0.f;
#pragma unroll
    for (int sp = 0; sp < 32; sp++)
        s += g_psum[sp*(B_*D_) + cidx] * __expf(g_pmax[sp*(B_*D_) + cidx] - m);
    g_cmax[cidx] = m;
    g_csum[cidx] = s;
}

// ---------------- stage5: attp[l][d] += v[t][l]*exp(k[t][d]-cmax), fp16 mma -
__global__ void __launch_bounds__(256) stage5_partial() {
    int bh = blockIdx.x;               // 0..31
    int b = bh >> 3, h = bh & 7;
    int sp = blockIdx.y;               // 0..15 (256 t each)

    __shared__ __align__(16) char vsT[16384];  // A: rows=l(128), 64 t halves/row
    __shared__ __align__(16) char ksT[16384];  // B: rows=d(128), 64 t halves/row
    uint32_t vbase = (uint32_t)__cvta_generic_to_shared(vsT);
    uint32_t kbase = (uint32_t)__cvta_generic_to_shared(ksT);

    int tid = threadIdx.x;
    int lane = tid & 31, wid = tid >> 5;
    int wm = wid & 3, wn = wid >> 2;
    int q = lane >> 3, r = lane & 7;
    int grp = lane >> 2, tg = lane & 3;

    int col = tid & 127;               // feature index
    int tq  = tid >> 7;                // 0/1
    float cm = g_cmax[b*D_ + h*128 + col];

    float acc[2][8][4];
#pragma unroll
    for (int i = 0; i < 2; i++)
#pragma unroll
        for (int j = 0; j < 8; j++)
#pragma unroll
            for (int e = 0; e < 4; e++) acc[i][j][e] = 0.f;

    for (int c = 0; c < 4; c++) {
        int t0 = sp*256 + c*64;
        __syncthreads();
#pragma unroll
        for (int i = 0; i < 4; i++) {
            int tsub = tq + i*2;       // 0..7, each 8 t values
            uint4 kp, vp;
            __half* khp = (__half*)&kp;
            __half* vhp = (__half*)&vp;
#pragma unroll
            for (int j = 0; j < 8; j++) {
                size_t off = ((size_t)(b*T_ + t0 + tsub*8 + j))*D_ + h*128 + col;
                khp[j] = __float2half_rn(__expf(__half2float(g_k[off]) - cm));
                vhp[j] = g_v[off];
            }
            unsigned ph = col*128 + ((tsub ^ (col & 7)) << 4);
            *(uint4*)(ksT + ph) = kp;
            *(uint4*)(vsT + ph) = vp;
        }
        __syncthreads();
#pragma unroll
        for (int ks = 0; ks < 4; ks++) {
            uint32_t a[2][4], bfr[4][4];
#pragma unroll
            for (int mi = 0; mi < 2; mi++) {
                int row = wm*32 + mi*16 + r + ((q & 1) << 3);
                int kh  = ks*16 + ((q >> 1) << 3);
                ldsm4(a[mi], vbase + row*128 + (((kh >> 3) ^ (row & 7)) << 4));
            }
#pragma unroll
            for (int nj = 0; nj < 4; nj++) {
                int nrow = wn*64 + nj*16 + r + ((q >> 1) << 3);
                int kh   = ks*16 + ((q & 1) << 3);
                ldsm4(bfr[nj], kbase + nrow*128 + (((kh >> 3) ^ (nrow & 7)) << 4));
            }
#pragma unroll
            for (int mi = 0; mi < 2; mi++)
#pragma unroll
                for (int nj = 0; nj < 4; nj++) {
                    mma16(acc[mi][nj*2 + 0], a[mi], &bfr[nj][0]);
                    mma16(acc[mi][nj*2 + 1], a[mi], &bfr[nj][2]);
                }
        }
    }

    float* outp = g_attp + ((size_t)(sp*32 + bh))*16384;   // [l][d]
#pragma unroll
    for (int mi = 0; mi < 2; mi++)
#pragma unroll
        for (int ni = 0; ni < 8; ni++) {
            int row = wm*32 + mi*16 + grp;       // l
            int cc  = wn*64 + ni*8 + tg*2;       // d
            *(float2*)(outp + row*128 + cc) =
                make_float2(acc[mi][ni][0], acc[mi][ni][1]);
            *(float2*)(outp + (row+8)*128 + cc) =
                make_float2(acc[mi][ni][2], acc[mi][ni][3]);
        }
}

// ---------------- reduce splits + divide by csum (fp16 out) ----------------
__global__ void stage5_reduce() {
    int idx = blockIdx.x*256 + threadIdx.x;    // 0..32*16384-1
    int bh = idx >> 14;
    int rem = idx & 16383;                      // l*128 + d
    int dd = rem & 127;
    int b = bh >> 3, h = bh & 7;
    float s = 0.f;
#pragma unroll
    for (int sp = 0; sp < 16; sp++) s += g_attp[((size_t)(sp*32 + bh))*16384 + rem];
    g_att[(size_t)bh*16384 + rem] = __float2half_rn(s / g_csum[b*D_ + h*128 + dd]);
}

// ---------------- stage6: y = softmax_hd(q) @ att, fp16 mma ----------------
__global__ void __launch_bounds__(256) stage6(float* __restrict__ out) {
    extern __shared__ char sm6[];
    char* qs   = sm6;            // 2 chunks x (128 rows x 128B)
    char* attB = sm6 + 32768;    // 2 chunks x (128 rows x 128B)
    uint32_t qbase = (uint32_t)__cvta_generic_to_shared(qs);
    uint32_t abase = (uint32_t)__cvta_generic_to_shared(attB);

    int rb = blockIdx.x;
    int h  = blockIdx.y;
    int r0 = rb * 128;
    int b  = r0 >> 12;
    const __half* attm = g_att + ((size_t)(b*8 + h))*16384;

    int tid = threadIdx.x;
    int lane = tid & 31, wid = tid >> 5;
    int wm = wid & 3, wn = wid >> 2;
    int q = lane >> 3, r = lane & 7;
    int grp = lane >> 2, tg = lane & 3;

    // async-load att tile: 2 chunks of 64 d, 128 l rows each
#pragma unroll
    for (int i = 0; i < 8; i++) {
        int idx = tid + i*256;          // 2048 16B-groups
        int c = idx >> 10;
        int rem = idx & 1023;
        int row = rem >> 3;
        int g = rem & 7;
        cp_async16(attB + c*16384 + row*128 + ((g ^ (row & 7)) << 4),
                   attm + row*128 + c*64 + g*8);
    }
    CP_COMMIT();

    // q softmax over head-dim: each warp 16 rows; store fp16 swizzled
    for (int rr = 0; rr < 16; rr++) {
        int rl = wid*16 + rr;
        const __half* qrow = g_q + (size_t)(r0 + rl)*D_ + h*128;
        float e[4];
        float mx = -1e30f;
#pragma unroll
        for (int j = 0; j < 4; j++) {
            e[j] = __half2float(qrow[lane + 32*j]);
            mx = fmaxf(mx, e[j]);
        }
#pragma unroll
        for (int o = 16; o; o >>= 1) mx = fmaxf(mx, __shfl_xor_sync(0xffffffffu, mx, o));
        float sm = 0.f;
#pragma unroll
        for (int j = 0; j < 4; j++) { e[j] = __expf(e[j] - mx); sm += e[j]; }
#pragma unroll
        for (int o = 16; o; o >>= 1) sm += __shfl_xor_sync(0xffffffffu, sm, o);
        float inv = 1.f / sm;
#pragma unroll
        for (int j = 0; j < 4; j++) {
            int d = lane + 32*j;
            int ch = d >> 6, d63 = d & 63;
            *(__half*)(qs + ch*16384 + rl*128 +
                       ((((d63 >> 3) ^ (rl & 7)) << 4) | ((d63 & 7)*2))) =
                __float2half_rn(e[j] * inv);
        }
    }
    CP_WAIT(0);
    __syncthreads();

    float acc[2][8][4];
#pragma unroll
    for (int i = 0; i < 2; i++)
#pragma unroll
        for (int j = 0; j < 8; j++)
#pragma unroll
            for (int e = 0; e < 4; e++) acc[i][j][e] = 0.f;

#pragma unroll
    for (int c = 0; c < 2; c++) {
        uint32_t Asm = qbase + c*16384;
        uint32_t Bsm = abase + c*16384;
#pragma unroll
        for (int ks = 0; ks < 4; ks++) {
            uint32_t a[2][4], bfr[4][4];
#pragma unroll
            for (int mi = 0; mi < 2; mi++) {
                int row = wm*32 + mi*16 + r + ((q & 1) << 3);
                int kh  = ks*16 + ((q >> 1) << 3);
                ldsm4(a[mi], Asm + row*128 + (((kh >> 3) ^ (row & 7)) << 4));
            }
#pragma unroll
            for (int nj = 0; nj < 4; nj++) {
                int nrow = wn*64 + nj*16 + r + ((q >> 1) << 3);
                int kh   = ks*16 + ((q & 1) << 3);
                ldsm4(bfr[nj], Bsm + nrow*128 + (((kh >> 3) ^ (nrow & 7)) << 4));
            }
#pragma unroll
            for (int mi = 0; mi < 2; mi++)
#pragma unroll
                for (int nj = 0; nj < 4; nj++) {
                    mma16(acc[mi][nj*2 + 0], a[mi], &bfr[nj][0]);
                    mma16(acc[mi][nj*2 + 1], a[mi], &bfr[nj][2]);
                }
        }
    }

#pragma unroll
    for (int mi = 0; mi < 2; mi++)
#pragma unroll
        for (int ni = 0; ni < 8; ni++) {
            int row = r0 + wm*32 + mi*16 + grp;
            int cc  = h*128 + wn*64 + ni*8 + tg*2;
            *(float2*)(out + (size_t)row*D_ + cc) =
                make_float2(acc[mi][ni][0], acc[mi][ni][1]);
            *(float2*)(out + (size_t)(row+8)*D_ + cc) =
                make_float2(acc[mi][ni][2], acc[mi][ni][3]);
        }
}

// ---------------------------------------------------------------------------
extern "C" void kernel_launch(void* const* d_in, const int* in_sizes, int n_in,
                              void* d_out, int out_size) {
    const float* x  = (const float*)d_in[0];
    const float* nw = (const float*)d_in[1];
    const float* nb = (const float*)d_in[2];
    const float* tw = (const float*)d_in[3];
    const float* tb = (const float*)d_in[4];
    const float* Wq = (const float*)d_in[5];
    const float* bq = (const float*)d_in[6];
    const float* Wk = (const float*)d_in[7];
    const float* bk = (const float*)d_in[8];
    const float* Wv = (const float*)d_in[9];
    const float* bv = (const float*)d_in[10];
    float* out = (float*)d_out;

    cudaFuncSetAttribute(gemm_f16, cudaFuncAttributeMaxDynamicSharedMemorySize, 98304);
    cudaFuncSetAttribute(stage6,   cudaFuncAttributeMaxDynamicSharedMemorySize, 65536);

    cvt_w<<<3072, 256>>>(Wq, Wk, Wv);
    ln_kernel<<<R_, 256>>>(x, nw, nb, tw, tb);

    gemm_f16<<<dim3(8, 128, 3), 256, 98304>>>(bq, bk, bv);

    kstats_part<<<dim3((B_*D_)/256, 32), 256>>>();
    kstats_combine<<<(B_*D_)/256, 256>>>();

    stage5_partial<<<dim3(32, 16), 256>>>();
    stage5_reduce<<<(32*16384)/256, 256>>>();

    stage6<<<dim3(128, 8), 256, 65536>>>(out);
}

// round 6
// speedup vs baseline: 2.7651x; 1.0011x over previous
#include <cuda_runtime.h>
#include <cuda_fp16.h>
#include <cstdint>

#define T_  4096
#define B_  4
#define D_  1024
#define H_  8
#define R_  (T_*B_)   // 16384 rows

// ---------------- scratch -------------------------------------------------
__device__ __align__(16) __half g_xn [(size_t)R_*D_];
__device__ __align__(16) __half g_xtn[(size_t)R_*D_];
__device__ __align__(16) __half g_q  [(size_t)R_*D_];
__device__ __align__(16) __half g_k  [(size_t)R_*D_];
__device__ __align__(16) __half g_v  [(size_t)R_*D_];
__device__ __align__(16) __half g_wh[3u*1024*1024];
__device__ __align__(16) float g_csum[B_*D_];
__device__ __align__(16) float g_attp[16ull*32*16384];   // [split][bh][l][d] fp32
__device__ __align__(16) __half g_att [(size_t)32*16384]; // [bh][l][d] fp16

// ---------------- helpers -------------------------------------------------
__device__ __forceinline__ void cp_async16(void* smem, const void* gmem) {
    unsigned sa = (unsigned)__cvta_generic_to_shared(smem);
    asm volatile("cp.async.cg.shared.global [%0], [%1], 16;\n" :: "r"(sa), "l"(gmem));
}
#define CP_COMMIT()  asm volatile("cp.async.commit_group;\n")
#define CP_WAIT(n)   asm volatile("cp.async.wait_group %0;\n" :: "n"(n))

__device__ __forceinline__ void mma16(float* d, const uint32_t* a, const uint32_t* b) {
    asm volatile(
        "mma.sync.aligned.m16n8k16.row.col.f32.f16.f16.f32 "
        "{%0,%1,%2,%3}, {%4,%5,%6,%7}, {%8,%9}, {%0,%1,%2,%3};"
        : "+f"(d[0]), "+f"(d[1]), "+f"(d[2]), "+f"(d[3])
        : "r"(a[0]), "r"(a[1]), "r"(a[2]), "r"(a[3]), "r"(b[0]), "r"(b[1]));
}
__device__ __forceinline__ void ldsm4(uint32_t* r, uint32_t addr) {
    asm volatile("ldmatrix.sync.aligned.m8n8.x4.shared.b16 {%0,%1,%2,%3}, [%4];"
        : "=r"(r[0]), "=r"(r[1]), "=r"(r[2]), "=r"(r[3]) : "r"(addr));
}

// ---------------- weight convert to fp16 ------------------------------------
__global__ void cvt_w(const float* __restrict__ w0, const float* __restrict__ w1,
                      const float* __restrict__ w2) {
    int i4 = blockIdx.x*256 + threadIdx.x;
    int which = i4 >> 18;
    int off = i4 & 262143;
    const float* s = (which == 0) ? w0 : (which == 1 ? w1 : w2);
    float4 v = *(const float4*)(s + (size_t)off*4);
    __half2 h0 = __floats2half2_rn(v.x, v.y);
    __half2 h1 = __floats2half2_rn(v.z, v.w);
    *(uint2*)(g_wh + (size_t)which*1048576 + (size_t)off*4) =
        make_uint2(*(unsigned*)&h0, *(unsigned*)&h1);
}

__global__ void zero_csum() {
    g_csum[blockIdx.x*256 + threadIdx.x] = 0.f;
}

// ---------------- LayerNorm (both branches, outputs fp16) ------------------
__global__ void ln_kernel(const float* __restrict__ x,
                          const float* __restrict__ nw, const float* __restrict__ nb,
                          const float* __restrict__ tw, const float* __restrict__ tb) {
    int rin = blockIdx.x;
    int t = rin / B_, b = rin % B_;
    const float* xr = x + (size_t)rin * D_;
    int tid = threadIdx.x;

    float v[4];
    float s = 0.f, s2 = 0.f;
#pragma unroll
    for (int j = 0; j < 4; j++) {
        v[j] = xr[tid + j*256];
        s  += v[j];
        s2 += v[j]*v[j];
    }
    __shared__ float red[40];
#pragma unroll
    for (int o = 16; o; o >>= 1) {
        s  += __shfl_xor_sync(0xffffffffu, s,  o);
        s2 += __shfl_xor_sync(0xffffffffu, s2, o);
    }
    if ((tid & 31) == 0) { red[tid>>5] = s; red[8 + (tid>>5)] = s2; }
    __syncthreads();
    if (tid < 32) {
        float a = (tid < 8) ? red[tid]     : 0.f;
        float c = (tid < 8) ? red[8 + tid] : 0.f;
#pragma unroll
        for (int o = 4; o; o >>= 1) {
            a += __shfl_xor_sync(0xffffffffu, a, o);
            c += __shfl_xor_sync(0xffffffffu, c, o);
        }
        if (tid == 0) { red[32] = a; red[33] = c; }
    }
    __syncthreads();
    float mean = red[32] * (1.f / D_);
    float var  = red[33] * (1.f / D_) - mean*mean;
    float rstd = rsqrtf(var + 1e-5f);

    size_t ro = ((size_t)b*T_ + t) * D_;
#pragma unroll
    for (int j = 0; j < 4; j++) {
        int d = tid + j*256;
        float z = (v[j] - mean) * rstd;
        g_xn [ro + d] = __float2half_rn(z * nw[d] + nb[d]);
        g_xtn[ro + d] = __float2half_rn(z * tw[d] + tb[d]);
    }
}

// ---------------- fp16 GEMM: C = A @ W^T + bias (fp16 out) -----------------
__global__ void __launch_bounds__(256, 2)
gemm_f16(int mode, const float* __restrict__ bias) {
    extern __shared__ char smraw[];
    uint32_t sbase = (uint32_t)__cvta_generic_to_shared(smraw);
    const __half* A = (mode == 0) ? g_xn : g_xtn;
    const __half* W = g_wh + (size_t)mode*1048576;
    __half*       C = (mode == 0) ? g_q : (mode == 1 ? g_k : g_v);

    int tid = threadIdx.x;
    int lane = tid & 31, wid = tid >> 5;
    int wm = wid & 3, wn = wid >> 2;
    int bm = blockIdx.y * 128, bn = blockIdx.x * 128;

    int q = lane >> 3, r = lane & 7;
    int grp = lane >> 2, tg = lane & 3;

    float acc[2][8][4];
#pragma unroll
    for (int i = 0; i < 2; i++)
#pragma unroll
        for (int j = 0; j < 8; j++)
#pragma unroll
            for (int e = 0; e < 4; e++) acc[i][j][e] = 0.f;

#define LOAD_CHUNK(S, KC)                                                        \
    {                                                                            \
        char* As_ = smraw + (S)*32768;                                           \
        char* Bs_ = As_ + 16384;                                                 \
        _Pragma("unroll")                                                        \
        for (int i = 0; i < 4; i++) {                                            \
            int idx = tid + i*256;                                               \
            int rr = idx >> 3, g = idx & 7;                                      \
            cp_async16(As_ + rr*128 + ((g ^ (rr & 7)) << 4),                     \
                       A + (size_t)(bm + rr)*1024 + (KC)*64 + g*8);              \
            cp_async16(Bs_ + rr*128 + ((g ^ (rr & 7)) << 4),                     \
                       W + (size_t)(bn + rr)*1024 + (KC)*64 + g*8);              \
        }                                                                        \
        CP_COMMIT();                                                             \
    }

    LOAD_CHUNK(0, 0)
    LOAD_CHUNK(1, 1)

    for (int c = 0; c < 16; c++) {
        if (c < 15) { CP_WAIT(1); } else { CP_WAIT(0); }
        __syncthreads();
        uint32_t Asm = sbase + (c % 3)*32768;
        uint32_t Bsm = Asm + 16384;

#pragma unroll
        for (int ks = 0; ks < 4; ks++) {
            uint32_t a[2][4], bfr[4][4];
#pragma unroll
            for (int mi = 0; mi < 2; mi++) {
                int row = wm*32 + mi*16 + r + ((q & 1) << 3);
                int kh  = ks*16 + ((q >> 1) << 3);
                ldsm4(a[mi], Asm + row*128 + (((kh >> 3) ^ (row & 7)) << 4));
            }
#pragma unroll
            for (int nj = 0; nj < 4; nj++) {
                int nrow = wn*64 + nj*16 + r + ((q >> 1) << 3);
                int kh   = ks*16 + ((q & 1) << 3);
                ldsm4(bfr[nj], Bsm + nrow*128 + (((kh >> 3) ^ (nrow & 7)) << 4));
            }
#pragma unroll
            for (int mi = 0; mi < 2; mi++)
#pragma unroll
                for (int nj = 0; nj < 4; nj++) {
                    mma16(acc[mi][nj*2 + 0], a[mi], &bfr[nj][0]);
                    mma16(acc[mi][nj*2 + 1], a[mi], &bfr[nj][2]);
                }
        }
        // no second barrier: prefetch target (c+2)%3 != compute buffer c%3,
        // and the chunk-top barrier bounds skew to one chunk.
        if (c + 2 < 16) { LOAD_CHUNK((c + 2) % 3, c + 2) }
    }
#undef LOAD_CHUNK

    const float* bias_ = bias;
#pragma unroll
    for (int mi = 0; mi < 2; mi++)
#pragma unroll
        for (int ni = 0; ni < 8; ni++) {
            int row = bm + wm*32 + mi*16 + grp;
            int col = bn + wn*64 + ni*8 + tg*2;
            float b0 = bias_[col], b1 = bias_[col + 1];
            __half2 lo = __floats2half2_rn(acc[mi][ni][0] + b0, acc[mi][ni][1] + b1);
            __half2 hi = __floats2half2_rn(acc[mi][ni][2] + b0, acc[mi][ni][3] + b1);
            *(__half2*)(C + (size_t)row*1024 + col) = lo;
            *(__half2*)(C + (size_t)(row + 8)*1024 + col) = hi;
        }
}

// ---------------- stage5: attp[l][d] += v[t][l]*exp(k[t][d]); csum atomics --
__global__ void __launch_bounds__(256) stage5_partial() {
    int bh = blockIdx.x;               // 0..31
    int b = bh >> 3, h = bh & 7;
    int sp = blockIdx.y;               // 0..15 (256 t each)

    __shared__ __align__(16) char vsT[16384];  // A: rows=l(128), 64 t halves/row
    __shared__ __align__(16) char ksT[16384];  // B: rows=d(128), 64 t halves/row
    uint32_t vbase = (uint32_t)__cvta_generic_to_shared(vsT);
    uint32_t kbase = (uint32_t)__cvta_generic_to_shared(ksT);

    int tid = threadIdx.x;
    int lane = tid & 31, wid = tid >> 5;
    int wm = wid & 3, wn = wid >> 2;
    int q = lane >> 3, r = lane & 7;
    int grp = lane >> 2, tg = lane & 3;

    int col = tid & 127;               // feature index
    int tq  = tid >> 7;                // 0/1

    float acc[2][8][4];
#pragma unroll
    for (int i = 0; i < 2; i++)
#pragma unroll
        for (int j = 0; j < 8; j++)
#pragma unroll
            for (int e = 0; e < 4; e++) acc[i][j][e] = 0.f;

    float esum = 0.f;                  // partial softmax denominator for (b, h*128+col)

    for (int c = 0; c < 4; c++) {
        int t0 = sp*256 + c*64;
        __syncthreads();
#pragma unroll
        for (int i = 0; i < 4; i++) {
            int tsub = tq + i*2;       // 0..7, each 8 t values
            uint4 kp, vp;
            __half* khp = (__half*)&kp;
            __half* vhp = (__half*)&vp;
#pragma unroll
            for (int j = 0; j < 8; j++) {
                size_t off = ((size_t)(b*T_ + t0 + tsub*8 + j))*D_ + h*128 + col;
                float e = __expf(__half2float(g_k[off]));
                esum += e;
                khp[j] = __float2half_rn(e);
                vhp[j] = g_v[off];
            }
            unsigned ph = col*128 + ((tsub ^ (col & 7)) << 4);
            *(uint4*)(ksT + ph) = kp;
            *(uint4*)(vsT + ph) = vp;
        }
        __syncthreads();
#pragma unroll
        for (int ks = 0; ks < 4; ks++) {
            uint32_t a[2][4], bfr[4][4];
#pragma unroll
            for (int mi = 0; mi < 2; mi++) {
                int row = wm*32 + mi*16 + r + ((q & 1) << 3);
                int kh  = ks*16 + ((q >> 1) << 3);
                ldsm4(a[mi], vbase + row*128 + (((kh >> 3) ^ (row & 7)) << 4));
            }
#pragma unroll
            for (int nj = 0; nj < 4; nj++) {
                int nrow = wn*64 + nj*16 + r + ((q >> 1) << 3);
                int kh   = ks*16 + ((q & 1) << 3);
                ldsm4(bfr[nj], kbase + nrow*128 + (((kh >> 3) ^ (nrow & 7)) << 4));
            }
#pragma unroll
            for (int mi = 0; mi < 2; mi++)
#pragma unroll
                for (int nj = 0; nj < 4; nj++) {
                    mma16(acc[mi][nj*2 + 0], a[mi], &bfr[nj][0]);
                    mma16(acc[mi][nj*2 + 1], a[mi], &bfr[nj][2]);
                }
        }
    }

    atomicAdd(&g_csum[b*D_ + h*128 + col], esum);

    float* outp = g_attp + ((size_t)(sp*32 + bh))*16384;   // [l][d]
#pragma unroll
    for (int mi = 0; mi < 2; mi++)
#pragma unroll
        for (int ni = 0; ni < 8; ni++) {
            int row = wm*32 + mi*16 + grp;       // l
            int cc  = wn*64 + ni*8 + tg*2;       // d
            *(float2*)(outp + row*128 + cc) =
                make_float2(acc[mi][ni][0], acc[mi][ni][1]);
            *(float2*)(outp + (row+8)*128 + cc) =
                make_float2(acc[mi][ni][2], acc[mi][ni][3]);
        }
}

// ---------------- reduce splits + divide by csum (fp16 out) ----------------
__global__ void stage5_reduce() {
    int idx = blockIdx.x*256 + threadIdx.x;    // 0..32*16384-1
    int bh = idx >> 14;
    int rem = idx & 16383;                      // l*128 + d
    int dd = rem & 127;
    int b = bh >> 3, h = bh & 7;
    float s = 0.f;
#pragma unroll
    for (int sp = 0; sp < 16; sp++) s += g_attp[((size_t)(sp*32 + bh))*16384 + rem];
    g_att[(size_t)bh*16384 + rem] = __float2half_rn(s / g_csum[b*D_ + h*128 + dd]);
}

// ---------------- stage6: y = softmax_hd(q) @ att, fp16 mma ----------------
__global__ void __launch_bounds__(256) stage6(float* __restrict__ out) {
    extern __shared__ char sm6[];
    char* qs   = sm6;            // 2 chunks x (128 rows x 128B)
    char* attB = sm6 + 32768;    // 2 chunks x (128 rows x 128B)
    uint32_t qbase = (uint32_t)__cvta_generic_to_shared(qs);
    uint32_t abase = (uint32_t)__cvta_generic_to_shared(attB);

    int rb = blockIdx.x;
    int h  = blockIdx.y;
    int r0 = rb * 128;
    int b  = r0 >> 12;
    const __half* attm = g_att + ((size_t)(b*8 + h))*16384;

    int tid = threadIdx.x;
    int lane = tid & 31, wid = tid >> 5;
    int wm = wid & 3, wn = wid >> 2;
    int q = lane >> 3, r = lane & 7;
    int grp = lane >> 2, tg = lane & 3;

#pragma unroll
    for (int i = 0; i < 8; i++) {
        int idx = tid + i*256;          // 2048 16B-groups
        int c = idx >> 10;
        int rem = idx & 1023;
        int row = rem >> 3;
        int g = rem & 7;
        cp_async16(attB + c*16384 + row*128 + ((g ^ (row & 7)) << 4),
                   attm + row*128 + c*64 + g*8);
    }
    CP_COMMIT();

    for (int rr = 0; rr < 16; rr++) {
        int rl = wid*16 + rr;
        const __half* qrow = g_q + (size_t)(r0 + rl)*D_ + h*128;
        float e[4];
        float mx = -1e30f;
#pragma unroll
        for (int j = 0; j < 4; j++) {
            e[j] = __half2float(qrow[lane + 32*j]);
            mx = fmaxf(mx, e[j]);
        }
#pragma unroll
        for (int o = 16; o; o >>= 1) mx = fmaxf(mx, __shfl_xor_sync(0xffffffffu, mx, o));
        float sm = 0.f;
#pragma unroll
        for (int j = 0; j < 4; j++) { e[j] = __expf(e[j] - mx); sm += e[j]; }
#pragma unroll
        for (int o = 16; o; o >>= 1) sm += __shfl_xor_sync(0xffffffffu, sm, o);
        float inv = 1.f / sm;
#pragma unroll
        for (int j = 0; j < 4; j++) {
            int d = lane + 32*j;
            int ch = d >> 6, d63 = d & 63;
            *(__half*)(qs + ch*16384 + rl*128 +
                       ((((d63 >> 3) ^ (rl & 7)) << 4) | ((d63 & 7)*2))) =
                __float2half_rn(e[j] * inv);
        }
    }
    CP_WAIT(0);
    __syncthreads();

    float acc[2][8][4];
#pragma unroll
    for (int i = 0; i < 2; i++)
#pragma unroll
        for (int j = 0; j < 8; j++)
#pragma unroll
            for (int e = 0; e < 4; e++) acc[i][j][e] = 0.f;

#pragma unroll
    for (int c = 0; c < 2; c++) {
        uint32_t Asm = qbase + c*16384;
        uint32_t Bsm = abase + c*16384;
#pragma unroll
        for (int ks = 0; ks < 4; ks++) {
            uint32_t a[2][4], bfr[4][4];
#pragma unroll
            for (int mi = 0; mi < 2; mi++) {
                int row = wm*32 + mi*16 + r + ((q & 1) << 3);
                int kh  = ks*16 + ((q >> 1) << 3);
                ldsm4(a[mi], Asm + row*128 + (((kh >> 3) ^ (row & 7)) << 4));
            }
#pragma unroll
            for (int nj = 0; nj < 4; nj++) {
                int nrow = wn*64 + nj*16 + r + ((q >> 1) << 3);
                int kh   = ks*16 + ((q & 1) << 3);
                ldsm4(bfr[nj], Bsm + nrow*128 + (((kh >> 3) ^ (nrow & 7)) << 4));
            }
#pragma unroll
            for (int mi = 0; mi < 2; mi++)
#pragma unroll
                for (int nj = 0; nj < 4; nj++) {
                    mma16(acc[mi][nj*2 + 0], a[mi], &bfr[nj][0]);
                    mma16(acc[mi][nj*2 + 1], a[mi], &bfr[nj][2]);
                }
        }
    }

#pragma unroll
    for (int mi = 0; mi < 2; mi++)
#pragma unroll
        for (int ni = 0; ni < 8; ni++) {
            int row = r0 + wm*32 + mi*16 + grp;
            int cc  = h*128 + wn*64 + ni*8 + tg*2;
            *(float2*)(out + (size_t)row*D_ + cc) =
                make_float2(acc[mi][ni][0], acc[mi][ni][1]);
            *(float2*)(out + (size_t)(row+8)*D_ + cc) =
                make_float2(acc[mi][ni][2], acc[mi][ni][3]);
        }
}

// ---------------------------------------------------------------------------
extern "C" void kernel_launch(void* const* d_in, const int* in_sizes, int n_in,
                              void* d_out, int out_size) {
    const float* x  = (const float*)d_in[0];
    const float* nw = (const float*)d_in[1];
    const float* nb = (const float*)d_in[2];
    const float* tw = (const float*)d_in[3];
    const float* tb = (const float*)d_in[4];
    const float* Wq = (const float*)d_in[5];
    const float* bq = (const float*)d_in[6];
    const float* Wk = (const float*)d_in[7];
    const float* bk = (const float*)d_in[8];
    const float* Wv = (const float*)d_in[9];
    const float* bv = (const float*)d_in[10];
    float* out = (float*)d_out;

    cudaFuncSetAttribute(gemm_f16, cudaFuncAttributeMaxDynamicSharedMemorySize, 98304);
    cudaFuncSetAttribute(stage6,   cudaFuncAttributeMaxDynamicSharedMemorySize, 65536);

    cvt_w<<<3072, 256>>>(Wq, Wk, Wv);                      // 0
    ln_kernel<<<R_, 256>>>(x, nw, nb, tw, tb);             // 1

    dim3 gg(8, 128);
    gemm_f16<<<gg, 256, 98304>>>(1, bk);                   // 2  k
    gemm_f16<<<gg, 256, 98304>>>(2, bv);                   // 3  v
    zero_csum<<<16, 256>>>();                              // 4
    gemm_f16<<<gg, 256, 98304>>>(0, bq);                   // 5  q  <- ncu captures this

    stage5_partial<<<dim3(32, 16), 256>>>();               // 6
    stage5_reduce<<<(32*16384)/256, 256>>>();              // 7
    stage6<<<dim3(128, 8), 256, 65536>>>(out);             // 8
}